// round 3
// baseline (speedup 1.0000x reference)
#include <cuda_runtime.h>
#include <cuda_bf16.h>
#include <stdint.h>

// Problem constants (shapes fixed by dataset; runtime n/E derived from in_sizes)
#define N_MAX 50000
#define E_MAX 1600000
#define IN_CH 128
#define HID 64
#define OUT 64

// ---- scratch (device globals: no allocation allowed) ----
__device__ __align__(16) float g_h1  [N_MAX * HID];   // relu(x@W1+b1)
__device__ __align__(16) float g_h2s [N_MAX * HID];   // dinv[n] * (h1@Wg)  (gather source)
__device__ __align__(16) float g_acc [N_MAX * HID];   // self-loop + scatter-add target
__device__ float g_degf[N_MAX];
__device__ float g_dinv[N_MAX];
__device__ float g_b2p[OUT];                          // bg@W2 + b2
__device__ int   g_is32;                              // 1 if edge_index is actually int32

// ---------------------------------------------------------------------------
// Detect edge_index dtype. int32 data read as int64 pairs gives values with a
// nonzero high word (>= 2^32 or negative) with overwhelming probability.
// Scan 32 entries across both the row and col halves.
// ---------------------------------------------------------------------------
__global__ void k_detect(const long long* __restrict__ ei, int n, int E) {
    if (blockIdx.x == 0 && threadIdx.x == 0) {
        int bad = 0;
        for (int i = 0; i < 16; i++) {
            long long a = ei[i];
            long long b = ei[E + i];      // col half (int64 view)
            if (a < 0 || a >= (long long)n) bad = 1;
            if (b < 0 || b >= (long long)n) bad = 1;
        }
        g_is32 = bad;
    }
}

// ---------------------------------------------------------------------------
// Degree (in-degree over col, +1 self loop) -> dinv = rsqrt(deg)
// ---------------------------------------------------------------------------
__global__ void k_deg_init(int n) {
    int i = blockIdx.x * blockDim.x + threadIdx.x;
    if (i < n) g_degf[i] = 1.0f;   // self loop
}

__global__ void k_deg_count(const void* __restrict__ ei_raw, int E) {
    for (int e = blockIdx.x * blockDim.x + threadIdx.x; e < E;
         e += gridDim.x * blockDim.x) {
        int c;
        if (g_is32) c = ((const int*)ei_raw)[E + e];
        else        c = (int)((const long long*)ei_raw)[E + e];
        atomicAdd(&g_degf[c], 1.0f);
    }
}

__global__ void k_dinv(int n) {
    int i = blockIdx.x * blockDim.x + threadIdx.x;
    if (i < n) g_dinv[i] = rsqrtf(g_degf[i]);
}

// ---------------------------------------------------------------------------
// lin1: h1 = relu(x @ W1 + b1).  Block = (64,4) threads, 8 nodes/block.
// W1 (128x64, 32KB) + x tile (8x128, 4KB) in smem.
// ---------------------------------------------------------------------------
__global__ __launch_bounds__(256) void k_lin1(const float* __restrict__ x,
                                              const float* __restrict__ W1,
                                              const float* __restrict__ b1, int n) {
    __shared__ float sW[IN_CH * HID];   // 32KB
    __shared__ float sX[8][IN_CH];      // 4KB
    __shared__ float sb[HID];
    const int tid = threadIdx.y * 64 + threadIdx.x;
    const int n0  = blockIdx.x * 8;

    for (int i = tid; i < IN_CH * HID; i += 256) sW[i] = W1[i];
    if (tid < HID) sb[tid] = b1[tid];
    for (int i = tid; i < 8 * IN_CH; i += 256) {
        int node = n0 + (i >> 7);
        sX[i >> 7][i & 127] = (node < n) ? x[(size_t)node * IN_CH + (i & 127)] : 0.0f;
    }
    __syncthreads();

    const int c = threadIdx.x;
    #pragma unroll
    for (int rr = 0; rr < 2; rr++) {
        int r = threadIdx.y + rr * 4;
        int node = n0 + r;
        if (node >= n) continue;
        float acc = sb[c];
        #pragma unroll
        for (int k = 0; k < IN_CH; k++)
            acc = fmaf(sX[r][k], sW[k * HID + c], acc);
        g_h1[(size_t)node * HID + c] = fmaxf(acc, 0.0f);
    }
}

// ---------------------------------------------------------------------------
// h2s = dinv[n] * (h1 @ Wg); also acc = h2s (self-loop init).
// Block = (64,4), 16 nodes/block. Wg (16KB) + h1 tile (4KB) in smem.
// ---------------------------------------------------------------------------
__global__ __launch_bounds__(256) void k_h2s(const float* __restrict__ Wg, int n) {
    __shared__ float sW[HID * HID];   // 16KB
    __shared__ float sH[16][HID];     // 4KB
    const int tid = threadIdx.y * 64 + threadIdx.x;
    const int n0  = blockIdx.x * 16;

    for (int i = tid; i < HID * HID; i += 256) sW[i] = Wg[i];
    for (int i = tid; i < 16 * HID; i += 256) {
        int node = n0 + (i >> 6);
        sH[i >> 6][i & 63] = (node < n) ? g_h1[(size_t)node * HID + (i & 63)] : 0.0f;
    }
    __syncthreads();

    const int c = threadIdx.x;
    #pragma unroll
    for (int rr = 0; rr < 4; rr++) {
        int r = threadIdx.y + rr * 4;
        int node = n0 + r;
        if (node >= n) continue;
        float acc = 0.0f;
        #pragma unroll
        for (int k = 0; k < HID; k++)
            acc = fmaf(sH[r][k], sW[k * HID + c], acc);
        float v = acc * g_dinv[node];
        size_t o = (size_t)node * HID + c;
        g_h2s[o] = v;
        g_acc[o] = v;
    }
}

// ---------------------------------------------------------------------------
// Edge scatter: acc[col] += h2s[row], 16 float4 chunks per edge,
// vector RED.128 atomics (both arrays L2-resident: 12.8MB each).
// ---------------------------------------------------------------------------
__global__ __launch_bounds__(256) void k_edge(const void* __restrict__ ei_raw, int E) {
    long long gid = (long long)blockIdx.x * blockDim.x + threadIdx.x;
    if (gid >= (long long)E * 16) return;
    const int e  = (int)(gid >> 4);
    const int ch = (int)(gid & 15);

    int r, c;
    if (g_is32) {
        const int* ei = (const int*)ei_raw;
        r = ei[e];
        c = ei[E + e];
    } else {
        const long long* ei = (const long long*)ei_raw;
        r = (int)ei[e];
        c = (int)ei[E + e];
    }

    const float4* src = reinterpret_cast<const float4*>(g_h2s) + (size_t)r * 16 + ch;
    float4 v = __ldg(src);
    float* p = g_acc + ((size_t)c * HID + ch * 4);
    asm volatile("red.global.add.v4.f32 [%0], {%1, %2, %3, %4};"
                 :: "l"(p), "f"(v.x), "f"(v.y), "f"(v.z), "f"(v.w) : "memory");
}

// ---------------------------------------------------------------------------
// b2' = bg @ W2 + b2   (one tiny block)
// ---------------------------------------------------------------------------
__global__ void k_b2p(const float* __restrict__ bg, const float* __restrict__ W2,
                      const float* __restrict__ b2) {
    int c = threadIdx.x;
    if (c < OUT) {
        float s = b2[c];
        #pragma unroll
        for (int k = 0; k < HID; k++) s = fmaf(bg[k], W2[k * OUT + c], s);
        g_b2p[c] = s;
    }
}

// ---------------------------------------------------------------------------
// out = (dinv[n] * acc[n]) @ W2 + b2'.  Same tiling as k_h2s.
// ---------------------------------------------------------------------------
__global__ __launch_bounds__(256) void k_out(const float* __restrict__ W2,
                                             float* __restrict__ out, int n) {
    __shared__ float sW[HID * OUT];   // 16KB
    __shared__ float sA[16][HID];     // 4KB
    __shared__ float sb[OUT];
    const int tid = threadIdx.y * 64 + threadIdx.x;
    const int n0  = blockIdx.x * 16;

    for (int i = tid; i < HID * OUT; i += 256) sW[i] = W2[i];
    if (tid < OUT) sb[tid] = g_b2p[tid];
    for (int i = tid; i < 16 * HID; i += 256) {
        int node = n0 + (i >> 6);
        sA[i >> 6][i & 63] =
            (node < n) ? g_acc[(size_t)node * HID + (i & 63)] * g_dinv[node] : 0.0f;
    }
    __syncthreads();

    const int c = threadIdx.x;
    #pragma unroll
    for (int rr = 0; rr < 4; rr++) {
        int r = threadIdx.y + rr * 4;
        int node = n0 + r;
        if (node >= n) continue;
        float acc = sb[c];
        #pragma unroll
        for (int k = 0; k < HID; k++)
            acc = fmaf(sA[r][k], sW[k * OUT + c], acc);
        out[(size_t)node * OUT + c] = acc;
    }
}

// ---------------------------------------------------------------------------
// Launch. Inputs (metadata order): x, edge_index, W1, b1, Wg, bg, W2, b2
// ---------------------------------------------------------------------------
extern "C" void kernel_launch(void* const* d_in, const int* in_sizes, int n_in,
                              void* d_out, int out_size) {
    const float* x  = (const float*)d_in[0];
    const void*  ei = d_in[1];                 // int64 (or int32 — detected)
    const float* W1 = (const float*)d_in[2];
    const float* b1 = (const float*)d_in[3];
    const float* Wg = (const float*)d_in[4];
    const float* bg = (const float*)d_in[5];
    const float* W2 = (const float*)d_in[6];
    const float* b2 = (const float*)d_in[7];
    float* out = (float*)d_out;

    const int n = in_sizes[0] / IN_CH;         // 50000
    const int E = in_sizes[1] / 2;             // 1.6M

    dim3 blk(64, 4);

    k_detect<<<1, 32>>>((const long long*)ei, n, E);
    k_deg_init<<<(n + 255) / 256, 256>>>(n);
    k_deg_count<<<2048, 256>>>(ei, E);
    k_dinv<<<(n + 255) / 256, 256>>>(n);

    k_lin1<<<(n + 7) / 8, blk>>>(x, W1, b1, n);
    k_h2s<<<(n + 15) / 16, blk>>>(Wg, n);

    long long edge_threads = (long long)E * 16;
    k_edge<<<(unsigned)((edge_threads + 255) / 256), 256>>>(ei, E);

    k_b2p<<<1, 64>>>(bg, W2, b2);
    k_out<<<(n + 15) / 16, blk>>>(W2, out, n);
}

// round 7
// speedup vs baseline: 1.6830x; 1.6830x over previous
#include <cuda_runtime.h>
#include <cuda_bf16.h>
#include <stdint.h>

#define N_MAX 50000
#define E_MAX 1600000
#define IN_CH 128
#define HID 64
#define OUT 64
#define XS 68   // smem row stride (floats) for 64-wide activation tiles

// ---- scratch (device globals: no allocation allowed) ----
__device__ __align__(16) float g_h1  [N_MAX * HID];   // relu(x@W1+b1)
__device__ __align__(16) float g_h2s [N_MAX * HID];   // dinv * (h1@Wg)
__device__ __align__(16) float g_acc [N_MAX * HID];   // self-loop init + scatter target
__device__ float g_degf[N_MAX];
__device__ float g_dinv[N_MAX];
__device__ float g_b2p[OUT];                          // bg@W2 + b2
__device__ int   g_is32;

// ---------------------------------------------------------------------------
// dtype sniff: int32 read as int64 -> out-of-range values with prob ~1
// ---------------------------------------------------------------------------
__global__ void k_detect(const long long* __restrict__ ei, int n, int E) {
    if (blockIdx.x == 0 && threadIdx.x == 0) {
        int bad = 0;
        for (int i = 0; i < 16; i++) {
            long long a = ei[i], b = ei[E + i];
            if (a < 0 || a >= (long long)n) bad = 1;
            if (b < 0 || b >= (long long)n) bad = 1;
        }
        g_is32 = bad;
    }
}

__global__ void k_deg_init(int n) {
    int i = blockIdx.x * blockDim.x + threadIdx.x;
    if (i < n) g_degf[i] = 1.0f;   // self loop
}

__global__ void k_deg_count(const void* __restrict__ ei_raw, int E) {
    for (int e = blockIdx.x * blockDim.x + threadIdx.x; e < E;
         e += gridDim.x * blockDim.x) {
        int c;
        if (g_is32) c = ((const int*)ei_raw)[E + e];
        else        c = (int)((const long long*)ei_raw)[E + e];
        atomicAdd(&g_degf[c], 1.0f);
    }
}

__global__ void k_dinv(int n) {
    int i = blockIdx.x * blockDim.x + threadIdx.x;
    if (i < n) g_dinv[i] = rsqrtf(g_degf[i]);
}

// ---------------------------------------------------------------------------
// 16 FMAs of a 4x4 register tile against a float4 of W and 4 scalars of A
// ---------------------------------------------------------------------------
#define TILE_FMA(acc, w, a0, a1, a2, a3)                                       \
    acc[0][0] = fmaf(a0, w.x, acc[0][0]); acc[0][1] = fmaf(a0, w.y, acc[0][1]);\
    acc[0][2] = fmaf(a0, w.z, acc[0][2]); acc[0][3] = fmaf(a0, w.w, acc[0][3]);\
    acc[1][0] = fmaf(a1, w.x, acc[1][0]); acc[1][1] = fmaf(a1, w.y, acc[1][1]);\
    acc[1][2] = fmaf(a1, w.z, acc[1][2]); acc[1][3] = fmaf(a1, w.w, acc[1][3]);\
    acc[2][0] = fmaf(a2, w.x, acc[2][0]); acc[2][1] = fmaf(a2, w.y, acc[2][1]);\
    acc[2][2] = fmaf(a2, w.z, acc[2][2]); acc[2][3] = fmaf(a2, w.w, acc[2][3]);\
    acc[3][0] = fmaf(a3, w.x, acc[3][0]); acc[3][1] = fmaf(a3, w.y, acc[3][1]);\
    acc[3][2] = fmaf(a3, w.z, acc[3][2]); acc[3][3] = fmaf(a3, w.w, acc[3][3])

// ---------------------------------------------------------------------------
// lin1: h1 = relu(x @ W1 + b1).  64 nodes x 64 cols per block, 256 threads,
// 4x4 register tile. K=128 processed in two 64-chunks so static smem fits:
// sW (64x64, 16KB) + sX (64xXS, 17.4KB) = 33.4KB.
// ---------------------------------------------------------------------------
__global__ __launch_bounds__(256) void k_lin1(const float* __restrict__ x,
                                              const float* __restrict__ W1,
                                              const float* __restrict__ b1, int n) {
    __shared__ float sW[64 * HID];    // current K-chunk of W1
    __shared__ float sX[64 * XS];     // current K-chunk of x tile
    const int tid = threadIdx.x;
    const int tx = tid & 15, ty = tid >> 4;
    const int n0 = blockIdx.x * 64;
    const int c0 = tx * 4, r0 = ty * 4;

    float4 bb = *(const float4*)(b1 + c0);
    float acc[4][4];
    #pragma unroll
    for (int i = 0; i < 4; i++) {
        acc[i][0] = bb.x; acc[i][1] = bb.y; acc[i][2] = bb.z; acc[i][3] = bb.w;
    }

    for (int kc = 0; kc < 2; kc++) {
        // stage W1 rows [kc*64, kc*64+64) (row-major [128][64])
        for (int i = tid; i < 64 * (HID / 4); i += 256)
            ((float4*)sW)[i] = ((const float4*)(W1 + kc * 64 * HID))[i];
        // stage x tile columns [kc*64, kc*64+64)
        for (int i = tid; i < 64 * 16; i += 256) {
            int r = i >> 4, c4 = i & 15;
            int node = n0 + r;
            float4 v = (node < n)
                ? *(const float4*)(x + (size_t)node * IN_CH + kc * 64 + c4 * 4)
                : make_float4(0.f, 0.f, 0.f, 0.f);
            *(float4*)(sX + r * XS + c4 * 4) = v;
        }
        __syncthreads();

        #pragma unroll 4
        for (int k = 0; k < 64; k++) {
            float4 w = *(const float4*)(sW + k * HID + c0);
            float a0 = sX[(r0 + 0) * XS + k];
            float a1 = sX[(r0 + 1) * XS + k];
            float a2 = sX[(r0 + 2) * XS + k];
            float a3 = sX[(r0 + 3) * XS + k];
            TILE_FMA(acc, w, a0, a1, a2, a3);
        }
        __syncthreads();
    }

    #pragma unroll
    for (int i = 0; i < 4; i++) {
        int node = n0 + r0 + i;
        if (node >= n) continue;
        float4 v = make_float4(fmaxf(acc[i][0], 0.f), fmaxf(acc[i][1], 0.f),
                               fmaxf(acc[i][2], 0.f), fmaxf(acc[i][3], 0.f));
        *(float4*)(g_h1 + (size_t)node * HID + c0) = v;
    }
}

// ---------------------------------------------------------------------------
// h2s = dinv * (h1 @ Wg); acc = h2s (self-loop init).
// 64x64 tile, 256 threads, 4x4 register tile. sWg 16KB + sH 17.4KB.
// ---------------------------------------------------------------------------
__global__ __launch_bounds__(256) void k_h2s(const float* __restrict__ Wg, int n) {
    __shared__ float sW[HID * HID];
    __shared__ float sH[64 * XS];
    const int tid = threadIdx.x;
    const int tx = tid & 15, ty = tid >> 4;
    const int n0 = blockIdx.x * 64;
    const int c0 = tx * 4, r0 = ty * 4;

    for (int i = tid; i < HID * HID / 4; i += 256)
        ((float4*)sW)[i] = ((const float4*)Wg)[i];
    for (int i = tid; i < 64 * 16; i += 256) {
        int r = i >> 4, c4 = i & 15;
        int node = n0 + r;
        float4 v = (node < n)
            ? ((const float4*)(g_h1 + (size_t)node * HID))[c4]
            : make_float4(0.f, 0.f, 0.f, 0.f);
        *(float4*)(sH + r * XS + c4 * 4) = v;
    }
    __syncthreads();

    float acc[4][4];
    #pragma unroll
    for (int i = 0; i < 4; i++)
        #pragma unroll
        for (int j = 0; j < 4; j++) acc[i][j] = 0.f;

    #pragma unroll 4
    for (int k = 0; k < HID; k++) {
        float4 w = *(const float4*)(sW + k * HID + c0);
        float a0 = sH[(r0 + 0) * XS + k];
        float a1 = sH[(r0 + 1) * XS + k];
        float a2 = sH[(r0 + 2) * XS + k];
        float a3 = sH[(r0 + 3) * XS + k];
        TILE_FMA(acc, w, a0, a1, a2, a3);
    }

    #pragma unroll
    for (int i = 0; i < 4; i++) {
        int node = n0 + r0 + i;
        if (node >= n) continue;
        float di = g_dinv[node];
        float4 v = make_float4(acc[i][0] * di, acc[i][1] * di,
                               acc[i][2] * di, acc[i][3] * di);
        size_t o = ((size_t)node * HID + c0) / 4;
        ((float4*)g_h2s)[o] = v;
        ((float4*)g_acc)[o] = v;
    }
}

// ---------------------------------------------------------------------------
// Edge scatter: acc[col] += h2s[row], 16 float4 chunks/edge, RED.128 atomics.
// ---------------------------------------------------------------------------
__global__ __launch_bounds__(256) void k_edge(const void* __restrict__ ei_raw, int E) {
    long long gid = (long long)blockIdx.x * blockDim.x + threadIdx.x;
    if (gid >= (long long)E * 16) return;
    const int e  = (int)(gid >> 4);
    const int ch = (int)(gid & 15);

    int r, c;
    if (g_is32) {
        const int* ei = (const int*)ei_raw;
        r = ei[e]; c = ei[E + e];
    } else {
        const long long* ei = (const long long*)ei_raw;
        r = (int)ei[e]; c = (int)ei[E + e];
    }

    float4 v = __ldg(reinterpret_cast<const float4*>(g_h2s) + (size_t)r * 16 + ch);
    float* p = g_acc + ((size_t)c * HID + ch * 4);
    asm volatile("red.global.add.v4.f32 [%0], {%1, %2, %3, %4};"
                 :: "l"(p), "f"(v.x), "f"(v.y), "f"(v.z), "f"(v.w) : "memory");
}

__global__ void k_b2p(const float* __restrict__ bg, const float* __restrict__ W2,
                      const float* __restrict__ b2) {
    int c = threadIdx.x;
    if (c < OUT) {
        float s = b2[c];
        #pragma unroll
        for (int k = 0; k < HID; k++) s = fmaf(bg[k], W2[k * OUT + c], s);
        g_b2p[c] = s;
    }
}

// ---------------------------------------------------------------------------
// out = (dinv * acc) @ W2 + b2'.  Same tiling as k_h2s.
// ---------------------------------------------------------------------------
__global__ __launch_bounds__(256) void k_out(const float* __restrict__ W2,
                                             float* __restrict__ out, int n) {
    __shared__ float sW[HID * OUT];
    __shared__ float sA[64 * XS];
    const int tid = threadIdx.x;
    const int tx = tid & 15, ty = tid >> 4;
    const int n0 = blockIdx.x * 64;
    const int c0 = tx * 4, r0 = ty * 4;

    for (int i = tid; i < HID * OUT / 4; i += 256)
        ((float4*)sW)[i] = ((const float4*)W2)[i];
    for (int i = tid; i < 64 * 16; i += 256) {
        int r = i >> 4, c4 = i & 15;
        int node = n0 + r;
        float4 v = make_float4(0.f, 0.f, 0.f, 0.f);
        if (node < n) {
            v = ((const float4*)(g_acc + (size_t)node * HID))[c4];
            float di = g_dinv[node];
            v.x *= di; v.y *= di; v.z *= di; v.w *= di;
        }
        *(float4*)(sA + r * XS + c4 * 4) = v;
    }
    __syncthreads();

    float4 bb = ((const float4*)g_b2p)[tx];
    float acc[4][4];
    #pragma unroll
    for (int i = 0; i < 4; i++) {
        acc[i][0] = bb.x; acc[i][1] = bb.y; acc[i][2] = bb.z; acc[i][3] = bb.w;
    }

    #pragma unroll 4
    for (int k = 0; k < HID; k++) {
        float4 w = *(const float4*)(sW + k * OUT + c0);
        float a0 = sA[(r0 + 0) * XS + k];
        float a1 = sA[(r0 + 1) * XS + k];
        float a2 = sA[(r0 + 2) * XS + k];
        float a3 = sA[(r0 + 3) * XS + k];
        TILE_FMA(acc, w, a0, a1, a2, a3);
    }

    #pragma unroll
    for (int i = 0; i < 4; i++) {
        int node = n0 + r0 + i;
        if (node >= n) continue;
        float4 v = make_float4(acc[i][0], acc[i][1], acc[i][2], acc[i][3]);
        *(float4*)(out + (size_t)node * OUT + c0) = v;
    }
}

// ---------------------------------------------------------------------------
// Inputs (metadata order): x, edge_index, W1, b1, Wg, bg, W2, b2
// ---------------------------------------------------------------------------
extern "C" void kernel_launch(void* const* d_in, const int* in_sizes, int n_in,
                              void* d_out, int out_size) {
    const float* x  = (const float*)d_in[0];
    const void*  ei = d_in[1];
    const float* W1 = (const float*)d_in[2];
    const float* b1 = (const float*)d_in[3];
    const float* Wg = (const float*)d_in[4];
    const float* bg = (const float*)d_in[5];
    const float* W2 = (const float*)d_in[6];
    const float* b2 = (const float*)d_in[7];
    float* out = (float*)d_out;

    const int n = in_sizes[0] / IN_CH;   // 50000
    const int E = in_sizes[1] / 2;       // 1.6M

    k_detect<<<1, 32>>>((const long long*)ei, n, E);
    k_deg_init<<<(n + 255) / 256, 256>>>(n);
    k_deg_count<<<2048, 256>>>(ei, E);
    k_dinv<<<(n + 255) / 256, 256>>>(n);

    k_lin1<<<(n + 63) / 64, 256>>>(x, W1, b1, n);
    k_h2s<<<(n + 63) / 64, 256>>>(Wg, n);

    long long edge_threads = (long long)E * 16;
    k_edge<<<(unsigned)((edge_threads + 255) / 256), 256>>>(ei, E);

    k_b2p<<<1, 64>>>(bg, W2, b2);
    k_out<<<(n + 63) / 64, 256>>>(W2, out, n);
}

// round 8
// speedup vs baseline: 1.7042x; 1.0126x over previous
#include <cuda_runtime.h>
#include <cuda_bf16.h>
#include <stdint.h>

#define N_MAX 50000
#define E_MAX 1600000
#define IN_CH 128
#define HID 64
#define OUT 64
#define XS 68   // smem row stride (floats) for 64-wide activation tiles

// ---- scratch (device globals: no allocation allowed) ----
__device__ __align__(16) float g_h1  [N_MAX * HID];   // relu(x@W1+b1)
__device__ __align__(16) float g_h2s [N_MAX * HID];   // dinv * (h1@Wg)
__device__ __align__(16) float g_acc [N_MAX * HID];   // self-loop init + scatter target
__device__ float g_degf[N_MAX];
__device__ float g_b2p[OUT];                          // bg@W2 + b2
__device__ int   g_is32;

// ---------------------------------------------------------------------------
// init degrees to 1 (self loop) + dtype sniff (block 0, thread 0):
// int32 data read as int64 -> out-of-range values with prob ~1
// ---------------------------------------------------------------------------
__global__ void k_init(const long long* __restrict__ ei, int n, int E) {
    int i = blockIdx.x * blockDim.x + threadIdx.x;
    if (i < n) g_degf[i] = 1.0f;
    if (blockIdx.x == 0 && threadIdx.x == 0) {
        int bad = 0;
        for (int j = 0; j < 16; j++) {
            long long a = ei[j], b = ei[E + j];
            if (a < 0 || a >= (long long)n) bad = 1;
            if (b < 0 || b >= (long long)n) bad = 1;
        }
        g_is32 = bad;
    }
}

__global__ void k_deg_count(const void* __restrict__ ei_raw, int E) {
    for (int e = blockIdx.x * blockDim.x + threadIdx.x; e < E;
         e += gridDim.x * blockDim.x) {
        int c;
        if (g_is32) c = ((const int*)ei_raw)[E + e];
        else        c = (int)((const long long*)ei_raw)[E + e];
        atomicAdd(&g_degf[c], 1.0f);
    }
}

// ---------------------------------------------------------------------------
// 16 FMAs of a 4x4 register tile against a float4 of W and 4 scalars of A
// ---------------------------------------------------------------------------
#define TILE_FMA(acc, w, a0, a1, a2, a3)                                       \
    acc[0][0] = fmaf(a0, w.x, acc[0][0]); acc[0][1] = fmaf(a0, w.y, acc[0][1]);\
    acc[0][2] = fmaf(a0, w.z, acc[0][2]); acc[0][3] = fmaf(a0, w.w, acc[0][3]);\
    acc[1][0] = fmaf(a1, w.x, acc[1][0]); acc[1][1] = fmaf(a1, w.y, acc[1][1]);\
    acc[1][2] = fmaf(a1, w.z, acc[1][2]); acc[1][3] = fmaf(a1, w.w, acc[1][3]);\
    acc[2][0] = fmaf(a2, w.x, acc[2][0]); acc[2][1] = fmaf(a2, w.y, acc[2][1]);\
    acc[2][2] = fmaf(a2, w.z, acc[2][2]); acc[2][3] = fmaf(a2, w.w, acc[2][3]);\
    acc[3][0] = fmaf(a3, w.x, acc[3][0]); acc[3][1] = fmaf(a3, w.y, acc[3][1]);\
    acc[3][2] = fmaf(a3, w.z, acc[3][2]); acc[3][3] = fmaf(a3, w.w, acc[3][3])

// ---------------------------------------------------------------------------
// lin1: h1 = relu(x @ W1 + b1).  64 nodes x 64 cols per block, 256 threads,
// 4x4 register tile. K=128 in two 64-chunks; static smem 33.4KB.
// ---------------------------------------------------------------------------
__global__ __launch_bounds__(256) void k_lin1(const float* __restrict__ x,
                                              const float* __restrict__ W1,
                                              const float* __restrict__ b1, int n) {
    __shared__ float sW[64 * HID];
    __shared__ float sX[64 * XS];
    const int tid = threadIdx.x;
    const int tx = tid & 15, ty = tid >> 4;
    const int n0 = blockIdx.x * 64;
    const int c0 = tx * 4, r0 = ty * 4;

    float4 bb = *(const float4*)(b1 + c0);
    float acc[4][4];
    #pragma unroll
    for (int i = 0; i < 4; i++) {
        acc[i][0] = bb.x; acc[i][1] = bb.y; acc[i][2] = bb.z; acc[i][3] = bb.w;
    }

    for (int kc = 0; kc < 2; kc++) {
        for (int i = tid; i < 64 * (HID / 4); i += 256)
            ((float4*)sW)[i] = ((const float4*)(W1 + kc * 64 * HID))[i];
        for (int i = tid; i < 64 * 16; i += 256) {
            int r = i >> 4, c4 = i & 15;
            int node = n0 + r;
            float4 v = (node < n)
                ? *(const float4*)(x + (size_t)node * IN_CH + kc * 64 + c4 * 4)
                : make_float4(0.f, 0.f, 0.f, 0.f);
            *(float4*)(sX + r * XS + c4 * 4) = v;
        }
        __syncthreads();

        #pragma unroll 4
        for (int k = 0; k < 64; k++) {
            float4 w = *(const float4*)(sW + k * HID + c0);
            float a0 = sX[(r0 + 0) * XS + k];
            float a1 = sX[(r0 + 1) * XS + k];
            float a2 = sX[(r0 + 2) * XS + k];
            float a3 = sX[(r0 + 3) * XS + k];
            TILE_FMA(acc, w, a0, a1, a2, a3);
        }
        __syncthreads();
    }

    #pragma unroll
    for (int i = 0; i < 4; i++) {
        int node = n0 + r0 + i;
        if (node >= n) continue;
        float4 v = make_float4(fmaxf(acc[i][0], 0.f), fmaxf(acc[i][1], 0.f),
                               fmaxf(acc[i][2], 0.f), fmaxf(acc[i][3], 0.f));
        *(float4*)(g_h1 + (size_t)node * HID + c0) = v;
    }
}

// ---------------------------------------------------------------------------
// h2s = rsqrt(deg) * (h1 @ Wg); acc = h2s (self-loop init).
// ---------------------------------------------------------------------------
__global__ __launch_bounds__(256) void k_h2s(const float* __restrict__ Wg, int n) {
    __shared__ float sW[HID * HID];
    __shared__ float sH[64 * XS];
    const int tid = threadIdx.x;
    const int tx = tid & 15, ty = tid >> 4;
    const int n0 = blockIdx.x * 64;
    const int c0 = tx * 4, r0 = ty * 4;

    for (int i = tid; i < HID * HID / 4; i += 256)
        ((float4*)sW)[i] = ((const float4*)Wg)[i];
    for (int i = tid; i < 64 * 16; i += 256) {
        int r = i >> 4, c4 = i & 15;
        int node = n0 + r;
        float4 v = (node < n)
            ? ((const float4*)(g_h1 + (size_t)node * HID))[c4]
            : make_float4(0.f, 0.f, 0.f, 0.f);
        *(float4*)(sH + r * XS + c4 * 4) = v;
    }
    __syncthreads();

    float acc[4][4];
    #pragma unroll
    for (int i = 0; i < 4; i++)
        #pragma unroll
        for (int j = 0; j < 4; j++) acc[i][j] = 0.f;

    #pragma unroll 4
    for (int k = 0; k < HID; k++) {
        float4 w = *(const float4*)(sW + k * HID + c0);
        float a0 = sH[(r0 + 0) * XS + k];
        float a1 = sH[(r0 + 1) * XS + k];
        float a2 = sH[(r0 + 2) * XS + k];
        float a3 = sH[(r0 + 3) * XS + k];
        TILE_FMA(acc, w, a0, a1, a2, a3);
    }

    #pragma unroll
    for (int i = 0; i < 4; i++) {
        int node = n0 + r0 + i;
        if (node >= n) continue;
        float di = rsqrtf(g_degf[node]);
        float4 v = make_float4(acc[i][0] * di, acc[i][1] * di,
                               acc[i][2] * di, acc[i][3] * di);
        size_t o = ((size_t)node * HID + c0) / 4;
        ((float4*)g_h2s)[o] = v;
        ((float4*)g_acc)[o] = v;
    }
}

// ---------------------------------------------------------------------------
// Edge scatter: acc[col] += h2s[row], 16 float4 chunks/edge, RED.128 atomics.
// ---------------------------------------------------------------------------
__global__ __launch_bounds__(256) void k_edge(const void* __restrict__ ei_raw, int E) {
    long long gid = (long long)blockIdx.x * blockDim.x + threadIdx.x;
    if (gid >= (long long)E * 16) return;
    const int e  = (int)(gid >> 4);
    const int ch = (int)(gid & 15);

    int r, c;
    if (g_is32) {
        const int* ei = (const int*)ei_raw;
        r = ei[e]; c = ei[E + e];
    } else {
        const long long* ei = (const long long*)ei_raw;
        r = (int)ei[e]; c = (int)ei[E + e];
    }

    float4 v = __ldg(reinterpret_cast<const float4*>(g_h2s) + (size_t)r * 16 + ch);
    float* p = g_acc + ((size_t)c * HID + ch * 4);
    asm volatile("red.global.add.v4.f32 [%0], {%1, %2, %3, %4};"
                 :: "l"(p), "f"(v.x), "f"(v.y), "f"(v.z), "f"(v.w) : "memory");
}

__global__ void k_b2p(const float* __restrict__ bg, const float* __restrict__ W2,
                      const float* __restrict__ b2) {
    int c = threadIdx.x;
    if (c < OUT) {
        float s = b2[c];
        #pragma unroll
        for (int k = 0; k < HID; k++) s = fmaf(bg[k], W2[k * OUT + c], s);
        g_b2p[c] = s;
    }
}

// ---------------------------------------------------------------------------
// out = (rsqrt(deg) * acc) @ W2 + b2'.
// ---------------------------------------------------------------------------
__global__ __launch_bounds__(256) void k_out(const float* __restrict__ W2,
                                             float* __restrict__ out, int n) {
    __shared__ float sW[HID * OUT];
    __shared__ float sA[64 * XS];
    const int tid = threadIdx.x;
    const int tx = tid & 15, ty = tid >> 4;
    const int n0 = blockIdx.x * 64;
    const int c0 = tx * 4, r0 = ty * 4;

    for (int i = tid; i < HID * OUT / 4; i += 256)
        ((float4*)sW)[i] = ((const float4*)W2)[i];
    for (int i = tid; i < 64 * 16; i += 256) {
        int r = i >> 4, c4 = i & 15;
        int node = n0 + r;
        float4 v = make_float4(0.f, 0.f, 0.f, 0.f);
        if (node < n) {
            v = ((const float4*)(g_acc + (size_t)node * HID))[c4];
            float di = rsqrtf(g_degf[node]);
            v.x *= di; v.y *= di; v.z *= di; v.w *= di;
        }
        *(float4*)(sA + r * XS + c4 * 4) = v;
    }
    __syncthreads();

    float4 bb = ((const float4*)g_b2p)[tx];
    float acc[4][4];
    #pragma unroll
    for (int i = 0; i < 4; i++) {
        acc[i][0] = bb.x; acc[i][1] = bb.y; acc[i][2] = bb.z; acc[i][3] = bb.w;
    }

    #pragma unroll 4
    for (int k = 0; k < HID; k++) {
        float4 w = *(const float4*)(sW + k * OUT + c0);
        float a0 = sA[(r0 + 0) * XS + k];
        float a1 = sA[(r0 + 1) * XS + k];
        float a2 = sA[(r0 + 2) * XS + k];
        float a3 = sA[(r0 + 3) * XS + k];
        TILE_FMA(acc, w, a0, a1, a2, a3);
    }

    #pragma unroll
    for (int i = 0; i < 4; i++) {
        int node = n0 + r0 + i;
        if (node >= n) continue;
        float4 v = make_float4(acc[i][0], acc[i][1], acc[i][2], acc[i][3]);
        *(float4*)(out + (size_t)node * OUT + c0) = v;
    }
}

// ---------------------------------------------------------------------------
// Inputs (metadata order): x, edge_index, W1, b1, Wg, bg, W2, b2
// ---------------------------------------------------------------------------
extern "C" void kernel_launch(void* const* d_in, const int* in_sizes, int n_in,
                              void* d_out, int out_size) {
    const float* x  = (const float*)d_in[0];
    const void*  ei = d_in[1];
    const float* W1 = (const float*)d_in[2];
    const float* b1 = (const float*)d_in[3];
    const float* Wg = (const float*)d_in[4];
    const float* bg = (const float*)d_in[5];
    const float* W2 = (const float*)d_in[6];
    const float* b2 = (const float*)d_in[7];
    float* out = (float*)d_out;

    const int n = in_sizes[0] / IN_CH;   // 50000
    const int E = in_sizes[1] / 2;       // 1.6M

    // launch order chosen so slot 4 = lin1, slot 6 = edge (ncu capture lands
    // on a kernel that matters, whichever offset the profiler uses)
    k_init<<<(n + 255) / 256, 256>>>((const long long*)ei, n, E);   // 1
    k_b2p<<<1, 64>>>(bg, W2, b2);                                   // 2
    k_deg_count<<<2048, 256>>>(ei, E);                              // 3
    k_lin1<<<(n + 63) / 64, 256>>>(x, W1, b1, n);                   // 4
    k_h2s<<<(n + 63) / 64, 256>>>(Wg, n);                           // 5
    long long edge_threads = (long long)E * 16;
    k_edge<<<(unsigned)((edge_threads + 255) / 256), 256>>>(ei, E); // 6
    k_out<<<(n + 63) / 64, 256>>>(W2, out, n);                      // 7
}

// round 11
// speedup vs baseline: 2.0447x; 1.1998x over previous
#include <cuda_runtime.h>
#include <cuda_bf16.h>
#include <stdint.h>

#define N_MAX 50000
#define E_MAX 1600000
#define IN_CH 128
#define HID 64
#define OUT 64
#define XS 68        // smem row stride (floats) for 64-wide activation tiles
#define SCAN_B 256   // scan chunk

// ---- scratch (device globals: no allocation allowed) ----
__device__ __align__(16) float g_h1  [N_MAX * HID];   // relu(x@W1+b1)
__device__ __align__(16) float g_h2s [N_MAX * HID];   // dinv * (h1@Wg)
__device__ __align__(16) float g_acc [N_MAX * HID];   // aggregated messages
__device__ int   g_degc  [N_MAX];                     // edge in-degree (no self loop)
__device__ int   g_start [N_MAX];                     // CSR offsets (exclusive scan)
__device__ int   g_cursor[N_MAX];
__device__ int   g_srcid [E_MAX];                     // CSR: source node per slot
__device__ int   g_bsum  [SCAN_B];                    // scan block sums
__device__ float g_b2p[OUT];                          // bg@W2 + b2
__device__ int   g_is32;

// ---------------------------------------------------------------------------
// zero degree/cursor + dtype sniff (int32 read as int64 -> out-of-range)
// ---------------------------------------------------------------------------
__global__ void k_init(const long long* __restrict__ ei, int n, int E) {
    int i = blockIdx.x * blockDim.x + threadIdx.x;
    if (i < n) { g_degc[i] = 0; g_cursor[i] = 0; }
    if (blockIdx.x == 0 && threadIdx.x == 0) {
        int bad = 0;
        for (int j = 0; j < 16; j++) {
            long long a = ei[j], b = ei[E + j];
            if (a < 0 || a >= (long long)n) bad = 1;
            if (b < 0 || b >= (long long)n) bad = 1;
        }
        g_is32 = bad;
    }
}

__global__ void k_deg_count(const void* __restrict__ ei_raw, int E) {
    for (int e = blockIdx.x * blockDim.x + threadIdx.x; e < E;
         e += gridDim.x * blockDim.x) {
        int c;
        if (g_is32) c = ((const int*)ei_raw)[E + e];
        else        c = (int)((const long long*)ei_raw)[E + e];
        atomicAdd(&g_degc[c], 1);
    }
}

// ---- 3-kernel exclusive prefix scan of g_degc into g_start -----------------
__global__ void k_scan1(int n) {
    __shared__ int s[SCAN_B];
    int t = threadIdx.x, i = blockIdx.x * SCAN_B + t;
    int v = (i < n) ? g_degc[i] : 0;
    s[t] = v; __syncthreads();
    for (int off = 1; off < SCAN_B; off <<= 1) {
        int add = (t >= off) ? s[t - off] : 0;
        __syncthreads();
        s[t] += add;
        __syncthreads();
    }
    if (i < n) g_start[i] = s[t] - v;          // exclusive within chunk
    if (t == SCAN_B - 1) g_bsum[blockIdx.x] = s[t];
}

__global__ void k_scan2(int nb) {
    __shared__ int s[SCAN_B];
    int t = threadIdx.x;
    int v = (t < nb) ? g_bsum[t] : 0;
    s[t] = v; __syncthreads();
    for (int off = 1; off < SCAN_B; off <<= 1) {
        int add = (t >= off) ? s[t - off] : 0;
        __syncthreads();
        s[t] += add;
        __syncthreads();
    }
    if (t < nb) g_bsum[t] = s[t] - v;          // exclusive block offsets
}

__global__ void k_scan3(int n) {
    int i = blockIdx.x * blockDim.x + threadIdx.x;
    if (i < n) g_start[i] += g_bsum[i / SCAN_B];
}

// ---- fill CSR: g_srcid[start[c] + cursor[c]++] = r -------------------------
__global__ void k_fill(const void* __restrict__ ei_raw, int E) {
    for (int e = blockIdx.x * blockDim.x + threadIdx.x; e < E;
         e += gridDim.x * blockDim.x) {
        int r, c;
        if (g_is32) {
            const int* ei = (const int*)ei_raw;
            r = ei[e]; c = ei[E + e];
        } else {
            const long long* ei = (const long long*)ei_raw;
            r = (int)ei[e]; c = (int)ei[E + e];
        }
        int pos = g_start[c] + atomicAdd(&g_cursor[c], 1);
        g_srcid[pos] = r;
    }
}

// ---------------------------------------------------------------------------
// GEMM helpers (no macros): 4x4 register tile, float4 operand loads
// ---------------------------------------------------------------------------
__device__ __forceinline__ float f4c(float4 v, int k) {
    return (k == 0) ? v.x : (k == 1) ? v.y : (k == 2) ? v.z : v.w;
}

__device__ __forceinline__ void tile_fma(float acc[4][4], float4 w,
                                         float a0, float a1, float a2, float a3) {
    acc[0][0] = fmaf(a0, w.x, acc[0][0]); acc[0][1] = fmaf(a0, w.y, acc[0][1]);
    acc[0][2] = fmaf(a0, w.z, acc[0][2]); acc[0][3] = fmaf(a0, w.w, acc[0][3]);
    acc[1][0] = fmaf(a1, w.x, acc[1][0]); acc[1][1] = fmaf(a1, w.y, acc[1][1]);
    acc[1][2] = fmaf(a1, w.z, acc[1][2]); acc[1][3] = fmaf(a1, w.w, acc[1][3]);
    acc[2][0] = fmaf(a2, w.x, acc[2][0]); acc[2][1] = fmaf(a2, w.y, acc[2][1]);
    acc[2][2] = fmaf(a2, w.z, acc[2][2]); acc[2][3] = fmaf(a2, w.w, acc[2][3]);
    acc[3][0] = fmaf(a3, w.x, acc[3][0]); acc[3][1] = fmaf(a3, w.y, acc[3][1]);
    acc[3][2] = fmaf(a3, w.z, acc[3][2]); acc[3][3] = fmaf(a3, w.w, acc[3][3]);
}

// 64-deep K loop: A rows from sA (stride XS), W rows from sW (stride wid)
__device__ __forceinline__ void gemm64(float acc[4][4], const float* sA,
                                       const float* sW, int r0, int c0, int wid) {
    #pragma unroll 4
    for (int k = 0; k < 64; k += 4) {
        float4 a0 = *(const float4*)(sA + (r0 + 0) * XS + k);
        float4 a1 = *(const float4*)(sA + (r0 + 1) * XS + k);
        float4 a2 = *(const float4*)(sA + (r0 + 2) * XS + k);
        float4 a3 = *(const float4*)(sA + (r0 + 3) * XS + k);
        #pragma unroll
        for (int kk = 0; kk < 4; kk++) {
            float4 w = *(const float4*)(sW + (k + kk) * wid + c0);
            tile_fma(acc, w, f4c(a0, kk), f4c(a1, kk), f4c(a2, kk), f4c(a3, kk));
        }
    }
}

// ---------------------------------------------------------------------------
// lin1: h1 = relu(x @ W1 + b1). 64x64 tile, 4x4 register tile, K in 2 chunks.
// ---------------------------------------------------------------------------
__global__ __launch_bounds__(256) void k_lin1(const float* __restrict__ x,
                                              const float* __restrict__ W1,
                                              const float* __restrict__ b1, int n) {
    __shared__ float sW[64 * HID];
    __shared__ float sX[64 * XS];
    const int tid = threadIdx.x;
    const int tx = tid & 15, ty = tid >> 4;
    const int n0 = blockIdx.x * 64;
    const int c0 = tx * 4, r0 = ty * 4;

    float4 bb = *(const float4*)(b1 + c0);
    float acc[4][4];
    #pragma unroll
    for (int i = 0; i < 4; i++) {
        acc[i][0] = bb.x; acc[i][1] = bb.y; acc[i][2] = bb.z; acc[i][3] = bb.w;
    }

    for (int kc = 0; kc < 2; kc++) {
        for (int i = tid; i < 64 * (HID / 4); i += 256)
            ((float4*)sW)[i] = ((const float4*)(W1 + kc * 64 * HID))[i];
        for (int i = tid; i < 64 * 16; i += 256) {
            int r = i >> 4, c4 = i & 15;
            int node = n0 + r;
            float4 v = (node < n)
                ? *(const float4*)(x + (size_t)node * IN_CH + kc * 64 + c4 * 4)
                : make_float4(0.f, 0.f, 0.f, 0.f);
            *(float4*)(sX + r * XS + c4 * 4) = v;
        }
        __syncthreads();
        gemm64(acc, sX, sW, r0, c0, HID);
        __syncthreads();
    }

    #pragma unroll
    for (int i = 0; i < 4; i++) {
        int node = n0 + r0 + i;
        if (node >= n) continue;
        float4 v = make_float4(fmaxf(acc[i][0], 0.f), fmaxf(acc[i][1], 0.f),
                               fmaxf(acc[i][2], 0.f), fmaxf(acc[i][3], 0.f));
        *(float4*)(g_h1 + (size_t)node * HID + c0) = v;
    }
}

// ---------------------------------------------------------------------------
// h2s = rsqrt(deg+1) * (h1 @ Wg)
// ---------------------------------------------------------------------------
__global__ __launch_bounds__(256) void k_h2s(const float* __restrict__ Wg, int n) {
    __shared__ float sW[HID * HID];
    __shared__ float sH[64 * XS];
    const int tid = threadIdx.x;
    const int tx = tid & 15, ty = tid >> 4;
    const int n0 = blockIdx.x * 64;
    const int c0 = tx * 4, r0 = ty * 4;

    for (int i = tid; i < HID * HID / 4; i += 256)
        ((float4*)sW)[i] = ((const float4*)Wg)[i];
    for (int i = tid; i < 64 * 16; i += 256) {
        int r = i >> 4, c4 = i & 15;
        int node = n0 + r;
        float4 v = (node < n)
            ? ((const float4*)(g_h1 + (size_t)node * HID))[c4]
            : make_float4(0.f, 0.f, 0.f, 0.f);
        *(float4*)(sH + r * XS + c4 * 4) = v;
    }
    __syncthreads();

    float acc[4][4];
    #pragma unroll
    for (int i = 0; i < 4; i++)
        #pragma unroll
        for (int j = 0; j < 4; j++) acc[i][j] = 0.f;

    gemm64(acc, sH, sW, r0, c0, HID);

    #pragma unroll
    for (int i = 0; i < 4; i++) {
        int node = n0 + r0 + i;
        if (node >= n) continue;
        float di = rsqrtf((float)(g_degc[node] + 1));
        float4 v = make_float4(acc[i][0] * di, acc[i][1] * di,
                               acc[i][2] * di, acc[i][3] * di);
        *(float4*)(g_h2s + (size_t)node * HID + c0) = v;
    }
}

// ---------------------------------------------------------------------------
// CSR gather: one warp per node; lane owns 2 channels (float2).
// acc = h2s[node] (self loop) + sum over incoming edges of h2s[src].
// ---------------------------------------------------------------------------
__global__ __launch_bounds__(256) void k_gather(int n) {
    const int warp = (blockIdx.x * 256 + threadIdx.x) >> 5;
    const int lane = threadIdx.x & 31;
    if (warp >= n) return;
    const int node = warp;
    const int beg = g_start[node];
    const int cnt = g_degc[node];

    const float2* __restrict__ src = (const float2*)g_h2s;
    float2 a = __ldg(&src[(size_t)node * 32 + lane]);   // self loop

    int j = 0;
    for (; j + 4 <= cnt; j += 4) {
        int r0 = __ldg(&g_srcid[beg + j + 0]);
        int r1 = __ldg(&g_srcid[beg + j + 1]);
        int r2 = __ldg(&g_srcid[beg + j + 2]);
        int r3 = __ldg(&g_srcid[beg + j + 3]);
        float2 v0 = __ldg(&src[(size_t)r0 * 32 + lane]);
        float2 v1 = __ldg(&src[(size_t)r1 * 32 + lane]);
        float2 v2 = __ldg(&src[(size_t)r2 * 32 + lane]);
        float2 v3 = __ldg(&src[(size_t)r3 * 32 + lane]);
        a.x += v0.x + v1.x + v2.x + v3.x;
        a.y += v0.y + v1.y + v2.y + v3.y;
    }
    for (; j < cnt; j++) {
        int r = __ldg(&g_srcid[beg + j]);
        float2 v = __ldg(&src[(size_t)r * 32 + lane]);
        a.x += v.x; a.y += v.y;
    }
    ((float2*)g_acc)[(size_t)node * 32 + lane] = a;
}

__global__ void k_b2p(const float* __restrict__ bg, const float* __restrict__ W2,
                      const float* __restrict__ b2) {
    int c = threadIdx.x;
    if (c < OUT) {
        float s = b2[c];
        #pragma unroll
        for (int k = 0; k < HID; k++) s = fmaf(bg[k], W2[k * OUT + c], s);
        g_b2p[c] = s;
    }
}

// ---------------------------------------------------------------------------
// out = (rsqrt(deg+1) * acc) @ W2 + b2'
// ---------------------------------------------------------------------------
__global__ __launch_bounds__(256) void k_out(const float* __restrict__ W2,
                                             float* __restrict__ out, int n) {
    __shared__ float sW[HID * OUT];
    __shared__ float sA[64 * XS];
    const int tid = threadIdx.x;
    const int tx = tid & 15, ty = tid >> 4;
    const int n0 = blockIdx.x * 64;
    const int c0 = tx * 4, r0 = ty * 4;

    for (int i = tid; i < HID * OUT / 4; i += 256)
        ((float4*)sW)[i] = ((const float4*)W2)[i];
    for (int i = tid; i < 64 * 16; i += 256) {
        int r = i >> 4, c4 = i & 15;
        int node = n0 + r;
        float4 v = make_float4(0.f, 0.f, 0.f, 0.f);
        if (node < n) {
            v = ((const float4*)(g_acc + (size_t)node * HID))[c4];
            float di = rsqrtf((float)(g_degc[node] + 1));
            v.x *= di; v.y *= di; v.z *= di; v.w *= di;
        }
        *(float4*)(sA + r * XS + c4 * 4) = v;
    }
    __syncthreads();

    float4 bb = ((const float4*)g_b2p)[tx];
    float acc[4][4];
    #pragma unroll
    for (int i = 0; i < 4; i++) {
        acc[i][0] = bb.x; acc[i][1] = bb.y; acc[i][2] = bb.z; acc[i][3] = bb.w;
    }

    gemm64(acc, sA, sW, r0, c0, OUT);

    #pragma unroll
    for (int i = 0; i < 4; i++) {
        int node = n0 + r0 + i;
        if (node >= n) continue;
        float4 v = make_float4(acc[i][0], acc[i][1], acc[i][2], acc[i][3]);
        *(float4*)(out + (size_t)node * OUT + c0) = v;
    }
}

// ---------------------------------------------------------------------------
// Inputs (metadata order): x, edge_index, W1, b1, Wg, bg, W2, b2
// ---------------------------------------------------------------------------
extern "C" void kernel_launch(void* const* d_in, const int* in_sizes, int n_in,
                              void* d_out, int out_size) {
    const float* x  = (const float*)d_in[0];
    const void*  ei = d_in[1];
    const float* W1 = (const float*)d_in[2];
    const float* b1 = (const float*)d_in[3];
    const float* Wg = (const float*)d_in[4];
    const float* bg = (const float*)d_in[5];
    const float* W2 = (const float*)d_in[6];
    const float* b2 = (const float*)d_in[7];
    float* out = (float*)d_out;

    const int n = in_sizes[0] / IN_CH;   // 50000
    const int E = in_sizes[1] / 2;       // 1.6M
    const int nb = (n + SCAN_B - 1) / SCAN_B;

    k_init<<<(n + 255) / 256, 256>>>((const long long*)ei, n, E);   // 1
    k_b2p<<<1, 64>>>(bg, W2, b2);                                   // 2
    k_deg_count<<<2048, 256>>>(ei, E);                              // 3
    k_lin1<<<(n + 63) / 64, 256>>>(x, W1, b1, n);                   // 4 (profiled)
    k_scan1<<<nb, SCAN_B>>>(n);                                     // 5
    k_scan2<<<1, SCAN_B>>>(nb);                                     // 6
    k_scan3<<<nb, SCAN_B>>>(n);                                     // 7
    k_fill<<<2048, 256>>>(ei, E);                                   // 8
    k_h2s<<<(n + 63) / 64, 256>>>(Wg, n);                           // 9
    k_gather<<<(n * 32 + 255) / 256, 256>>>(n);                     // 10
    k_out<<<(n + 63) / 64, 256>>>(W2, out, n);                      // 11
}

// round 12
// speedup vs baseline: 2.0605x; 1.0077x over previous
#include <cuda_runtime.h>
#include <cuda_fp16.h>
#include <stdint.h>

#define N_MAX 50000
#define E_MAX 1600000
#define IN_CH 128
#define HID 64
#define OUT 64
#define XS 68        // smem row stride (floats) for 64-wide activation tiles
#define SCAN_B 256   // scan chunk

// ---- scratch (device globals: no allocation allowed) ----
__device__ __align__(16) float  g_h1  [N_MAX * HID];  // relu(x@W1+b1)
__device__ __align__(16) __half g_h2s [N_MAX * HID];  // fp16(dinv * (h1@Wg))
__device__ __align__(16) float  g_acc [N_MAX * HID];  // aggregated messages (fp32)
__device__ int   g_degc  [N_MAX];                     // edge in-degree (no self loop)
__device__ int   g_start [N_MAX];                     // CSR offsets (exclusive scan)
__device__ int   g_cursor[N_MAX];
__device__ int   g_srcid [E_MAX];                     // CSR: source node per slot
__device__ int   g_bsum  [SCAN_B];                    // scan block sums
__device__ float g_b2p[OUT];                          // bg@W2 + b2
__device__ int   g_is32;

// ---------------------------------------------------------------------------
// zero degree/cursor + dtype sniff (int32 read as int64 -> out-of-range)
// ---------------------------------------------------------------------------
__global__ void k_init(const long long* __restrict__ ei, int n, int E) {
    int i = blockIdx.x * blockDim.x + threadIdx.x;
    if (i < n) { g_degc[i] = 0; g_cursor[i] = 0; }
    if (blockIdx.x == 0 && threadIdx.x == 0) {
        int bad = 0;
        for (int j = 0; j < 16; j++) {
            long long a = ei[j], b = ei[E + j];
            if (a < 0 || a >= (long long)n) bad = 1;
            if (b < 0 || b >= (long long)n) bad = 1;
        }
        g_is32 = bad;
    }
}

__global__ void k_deg_count(const void* __restrict__ ei_raw, int E) {
    for (int e = blockIdx.x * blockDim.x + threadIdx.x; e < E;
         e += gridDim.x * blockDim.x) {
        int c;
        if (g_is32) c = ((const int*)ei_raw)[E + e];
        else        c = (int)((const long long*)ei_raw)[E + e];
        atomicAdd(&g_degc[c], 1);
    }
}

// ---- 3-kernel exclusive prefix scan of g_degc into g_start -----------------
__global__ void k_scan1(int n) {
    __shared__ int s[SCAN_B];
    int t = threadIdx.x, i = blockIdx.x * SCAN_B + t;
    int v = (i < n) ? g_degc[i] : 0;
    s[t] = v; __syncthreads();
    for (int off = 1; off < SCAN_B; off <<= 1) {
        int add = (t >= off) ? s[t - off] : 0;
        __syncthreads();
        s[t] += add;
        __syncthreads();
    }
    if (i < n) g_start[i] = s[t] - v;          // exclusive within chunk
    if (t == SCAN_B - 1) g_bsum[blockIdx.x] = s[t];
}

__global__ void k_scan2(int nb) {
    __shared__ int s[SCAN_B];
    int t = threadIdx.x;
    int v = (t < nb) ? g_bsum[t] : 0;
    s[t] = v; __syncthreads();
    for (int off = 1; off < SCAN_B; off <<= 1) {
        int add = (t >= off) ? s[t - off] : 0;
        __syncthreads();
        s[t] += add;
        __syncthreads();
    }
    if (t < nb) g_bsum[t] = s[t] - v;          // exclusive block offsets
}

__global__ void k_scan3(int n) {
    int i = blockIdx.x * blockDim.x + threadIdx.x;
    if (i < n) g_start[i] += g_bsum[i / SCAN_B];
}

// ---- fill CSR: g_srcid[start[c] + cursor[c]++] = r -------------------------
__global__ void k_fill(const void* __restrict__ ei_raw, int E) {
    for (int e = blockIdx.x * blockDim.x + threadIdx.x; e < E;
         e += gridDim.x * blockDim.x) {
        int r, c;
        if (g_is32) {
            const int* ei = (const int*)ei_raw;
            r = ei[e]; c = ei[E + e];
        } else {
            const long long* ei = (const long long*)ei_raw;
            r = (int)ei[e]; c = (int)ei[E + e];
        }
        int pos = g_start[c] + atomicAdd(&g_cursor[c], 1);
        g_srcid[pos] = r;
    }
}

// ---------------------------------------------------------------------------
// GEMM helpers: 4x4 register tile, float4 operand loads
// ---------------------------------------------------------------------------
__device__ __forceinline__ float f4c(float4 v, int k) {
    return (k == 0) ? v.x : (k == 1) ? v.y : (k == 2) ? v.z : v.w;
}

__device__ __forceinline__ void tile_fma(float acc[4][4], float4 w,
                                         float a0, float a1, float a2, float a3) {
    acc[0][0] = fmaf(a0, w.x, acc[0][0]); acc[0][1] = fmaf(a0, w.y, acc[0][1]);
    acc[0][2] = fmaf(a0, w.z, acc[0][2]); acc[0][3] = fmaf(a0, w.w, acc[0][3]);
    acc[1][0] = fmaf(a1, w.x, acc[1][0]); acc[1][1] = fmaf(a1, w.y, acc[1][1]);
    acc[1][2] = fmaf(a1, w.z, acc[1][2]); acc[1][3] = fmaf(a1, w.w, acc[1][3]);
    acc[2][0] = fmaf(a2, w.x, acc[2][0]); acc[2][1] = fmaf(a2, w.y, acc[2][1]);
    acc[2][2] = fmaf(a2, w.z, acc[2][2]); acc[2][3] = fmaf(a2, w.w, acc[2][3]);
    acc[3][0] = fmaf(a3, w.x, acc[3][0]); acc[3][1] = fmaf(a3, w.y, acc[3][1]);
    acc[3][2] = fmaf(a3, w.z, acc[3][2]); acc[3][3] = fmaf(a3, w.w, acc[3][3]);
}

__device__ __forceinline__ void gemm64(float acc[4][4], const float* sA,
                                       const float* sW, int r0, int c0, int wid) {
    #pragma unroll 4
    for (int k = 0; k < 64; k += 4) {
        float4 a0 = *(const float4*)(sA + (r0 + 0) * XS + k);
        float4 a1 = *(const float4*)(sA + (r0 + 1) * XS + k);
        float4 a2 = *(const float4*)(sA + (r0 + 2) * XS + k);
        float4 a3 = *(const float4*)(sA + (r0 + 3) * XS + k);
        #pragma unroll
        for (int kk = 0; kk < 4; kk++) {
            float4 w = *(const float4*)(sW + (k + kk) * wid + c0);
            tile_fma(acc, w, f4c(a0, kk), f4c(a1, kk), f4c(a2, kk), f4c(a3, kk));
        }
    }
}

// ---------------------------------------------------------------------------
// lin1: h1 = relu(x @ W1 + b1). 64x64 tile, 4x4 register tile, K in 2 chunks.
// ---------------------------------------------------------------------------
__global__ __launch_bounds__(256) void k_lin1(const float* __restrict__ x,
                                              const float* __restrict__ W1,
                                              const float* __restrict__ b1, int n) {
    __shared__ float sW[64 * HID];
    __shared__ float sX[64 * XS];
    const int tid = threadIdx.x;
    const int tx = tid & 15, ty = tid >> 4;
    const int n0 = blockIdx.x * 64;
    const int c0 = tx * 4, r0 = ty * 4;

    float4 bb = *(const float4*)(b1 + c0);
    float acc[4][4];
    #pragma unroll
    for (int i = 0; i < 4; i++) {
        acc[i][0] = bb.x; acc[i][1] = bb.y; acc[i][2] = bb.z; acc[i][3] = bb.w;
    }

    for (int kc = 0; kc < 2; kc++) {
        for (int i = tid; i < 64 * (HID / 4); i += 256)
            ((float4*)sW)[i] = ((const float4*)(W1 + kc * 64 * HID))[i];
        for (int i = tid; i < 64 * 16; i += 256) {
            int r = i >> 4, c4 = i & 15;
            int node = n0 + r;
            float4 v = (node < n)
                ? *(const float4*)(x + (size_t)node * IN_CH + kc * 64 + c4 * 4)
                : make_float4(0.f, 0.f, 0.f, 0.f);
            *(float4*)(sX + r * XS + c4 * 4) = v;
        }
        __syncthreads();
        gemm64(acc, sX, sW, r0, c0, HID);
        __syncthreads();
    }

    #pragma unroll
    for (int i = 0; i < 4; i++) {
        int node = n0 + r0 + i;
        if (node >= n) continue;
        float4 v = make_float4(fmaxf(acc[i][0], 0.f), fmaxf(acc[i][1], 0.f),
                               fmaxf(acc[i][2], 0.f), fmaxf(acc[i][3], 0.f));
        *(float4*)(g_h1 + (size_t)node * HID + c0) = v;
    }
}

// ---------------------------------------------------------------------------
// h2s = fp16( rsqrt(deg+1) * (h1 @ Wg) )   -- message payload stored as half2
// ---------------------------------------------------------------------------
__global__ __launch_bounds__(256) void k_h2s(const float* __restrict__ Wg, int n) {
    __shared__ float sW[HID * HID];
    __shared__ float sH[64 * XS];
    const int tid = threadIdx.x;
    const int tx = tid & 15, ty = tid >> 4;
    const int n0 = blockIdx.x * 64;
    const int c0 = tx * 4, r0 = ty * 4;

    for (int i = tid; i < HID * HID / 4; i += 256)
        ((float4*)sW)[i] = ((const float4*)Wg)[i];
    for (int i = tid; i < 64 * 16; i += 256) {
        int r = i >> 4, c4 = i & 15;
        int node = n0 + r;
        float4 v = (node < n)
            ? ((const float4*)(g_h1 + (size_t)node * HID))[c4]
            : make_float4(0.f, 0.f, 0.f, 0.f);
        *(float4*)(sH + r * XS + c4 * 4) = v;
    }
    __syncthreads();

    float acc[4][4];
    #pragma unroll
    for (int i = 0; i < 4; i++)
        #pragma unroll
        for (int j = 0; j < 4; j++) acc[i][j] = 0.f;

    gemm64(acc, sH, sW, r0, c0, HID);

    #pragma unroll
    for (int i = 0; i < 4; i++) {
        int node = n0 + r0 + i;
        if (node >= n) continue;
        float di = rsqrtf((float)(g_degc[node] + 1));
        __half2 h01 = __floats2half2_rn(acc[i][0] * di, acc[i][1] * di);
        __half2 h23 = __floats2half2_rn(acc[i][2] * di, acc[i][3] * di);
        __half2* dst = (__half2*)(g_h2s + (size_t)node * HID + c0);
        dst[0] = h01;
        dst[1] = h23;
    }
}

// ---------------------------------------------------------------------------
// CSR gather: one warp per node; lane owns 2 channels (half2 payload,
// fp32 accumulation). acc = h2s[node] (self loop) + sum of h2s[src].
// ---------------------------------------------------------------------------
__global__ __launch_bounds__(256) void k_gather(int n) {
    const int warp = (blockIdx.x * 256 + threadIdx.x) >> 5;
    const int lane = threadIdx.x & 31;
    if (warp >= n) return;
    const int node = warp;
    const int beg = g_start[node];
    const int cnt = g_degc[node];

    const __half2* __restrict__ src = (const __half2*)g_h2s;
    float2 sf = __half22float2(__ldg(&src[(size_t)node * 32 + lane]));  // self loop
    float ax = sf.x, ay = sf.y;

    int j = 0;
    for (; j + 4 <= cnt; j += 4) {
        int r0 = __ldg(&g_srcid[beg + j + 0]);
        int r1 = __ldg(&g_srcid[beg + j + 1]);
        int r2 = __ldg(&g_srcid[beg + j + 2]);
        int r3 = __ldg(&g_srcid[beg + j + 3]);
        float2 v0 = __half22float2(__ldg(&src[(size_t)r0 * 32 + lane]));
        float2 v1 = __half22float2(__ldg(&src[(size_t)r1 * 32 + lane]));
        float2 v2 = __half22float2(__ldg(&src[(size_t)r2 * 32 + lane]));
        float2 v3 = __half22float2(__ldg(&src[(size_t)r3 * 32 + lane]));
        ax += v0.x + v1.x + v2.x + v3.x;
        ay += v0.y + v1.y + v2.y + v3.y;
    }
    for (; j < cnt; j++) {
        int r = __ldg(&g_srcid[beg + j]);
        float2 v = __half22float2(__ldg(&src[(size_t)r * 32 + lane]));
        ax += v.x; ay += v.y;
    }
    ((float2*)g_acc)[(size_t)node * 32 + lane] = make_float2(ax, ay);
}

__global__ void k_b2p(const float* __restrict__ bg, const float* __restrict__ W2,
                      const float* __restrict__ b2) {
    int c = threadIdx.x;
    if (c < OUT) {
        float s = b2[c];
        #pragma unroll
        for (int k = 0; k < HID; k++) s = fmaf(bg[k], W2[k * OUT + c], s);
        g_b2p[c] = s;
    }
}

// ---------------------------------------------------------------------------
// out = (rsqrt(deg+1) * acc) @ W2 + b2'
// ---------------------------------------------------------------------------
__global__ __launch_bounds__(256) void k_out(const float* __restrict__ W2,
                                             float* __restrict__ out, int n) {
    __shared__ float sW[HID * OUT];
    __shared__ float sA[64 * XS];
    const int tid = threadIdx.x;
    const int tx = tid & 15, ty = tid >> 4;
    const int n0 = blockIdx.x * 64;
    const int c0 = tx * 4, r0 = ty * 4;

    for (int i = tid; i < HID * OUT / 4; i += 256)
        ((float4*)sW)[i] = ((const float4*)W2)[i];
    for (int i = tid; i < 64 * 16; i += 256) {
        int r = i >> 4, c4 = i & 15;
        int node = n0 + r;
        float4 v = make_float4(0.f, 0.f, 0.f, 0.f);
        if (node < n) {
            v = ((const float4*)(g_acc + (size_t)node * HID))[c4];
            float di = rsqrtf((float)(g_degc[node] + 1));
            v.x *= di; v.y *= di; v.z *= di; v.w *= di;
        }
        *(float4*)(sA + r * XS + c4 * 4) = v;
    }
    __syncthreads();

    float4 bb = ((const float4*)g_b2p)[tx];
    float acc[4][4];
    #pragma unroll
    for (int i = 0; i < 4; i++) {
        acc[i][0] = bb.x; acc[i][1] = bb.y; acc[i][2] = bb.z; acc[i][3] = bb.w;
    }

    gemm64(acc, sA, sW, r0, c0, OUT);

    #pragma unroll
    for (int i = 0; i < 4; i++) {
        int node = n0 + r0 + i;
        if (node >= n) continue;
        float4 v = make_float4(acc[i][0], acc[i][1], acc[i][2], acc[i][3]);
        *(float4*)(out + (size_t)node * OUT + c0) = v;
    }
}

// ---------------------------------------------------------------------------
// Inputs (metadata order): x, edge_index, W1, b1, Wg, bg, W2, b2
// ---------------------------------------------------------------------------
extern "C" void kernel_launch(void* const* d_in, const int* in_sizes, int n_in,
                              void* d_out, int out_size) {
    const float* x  = (const float*)d_in[0];
    const void*  ei = d_in[1];
    const float* W1 = (const float*)d_in[2];
    const float* b1 = (const float*)d_in[3];
    const float* Wg = (const float*)d_in[4];
    const float* bg = (const float*)d_in[5];
    const float* W2 = (const float*)d_in[6];
    const float* b2 = (const float*)d_in[7];
    float* out = (float*)d_out;

    const int n = in_sizes[0] / IN_CH;   // 50000
    const int E = in_sizes[1] / 2;       // 1.6M
    const int nb = (n + SCAN_B - 1) / SCAN_B;

    k_init<<<(n + 255) / 256, 256>>>((const long long*)ei, n, E);   // 1
    k_b2p<<<1, 64>>>(bg, W2, b2);                                   // 2
    k_deg_count<<<2048, 256>>>(ei, E);                              // 3
    k_lin1<<<(n + 63) / 64, 256>>>(x, W1, b1, n);                   // 4 (profiled)
    k_scan1<<<nb, SCAN_B>>>(n);                                     // 5
    k_scan2<<<1, SCAN_B>>>(nb);                                     // 6
    k_scan3<<<nb, SCAN_B>>>(n);                                     // 7
    k_fill<<<2048, 256>>>(ei, E);                                   // 8
    k_h2s<<<(n + 63) / 64, 256>>>(Wg, n);                           // 9
    k_gather<<<(n * 32 + 255) / 256, 256>>>(n);                     // 10
    k_out<<<(n + 63) / 64, 256>>>(W2, out, n);                      // 11
}

// round 14
// speedup vs baseline: 2.0910x; 1.0148x over previous
#include <cuda_runtime.h>
#include <cuda_fp16.h>
#include <stdint.h>

#define N_MAX 50000
#define E_MAX 1600000
#define IN_CH 128
#define HID 64
#define OUT 64
#define XS 68        // smem row stride (floats) for 64-wide activation tiles
#define SCAN_B 256   // scan chunk

// ---- scratch (device globals: no allocation allowed) ----
__device__ __align__(16) float  g_h1  [N_MAX * HID];  // relu(x@W1+b1)
__device__ __align__(16) __half g_h2s [N_MAX * HID];  // fp16(dinv * (h1@Wg))
__device__ __align__(16) float  g_acc [N_MAX * HID];  // aggregated messages (fp32)
__device__ int   g_degc  [N_MAX];                     // edge in-degree (no self loop)
__device__ int   g_start [N_MAX];                     // CSR offsets (exclusive scan)
__device__ int   g_cursor[N_MAX];
__device__ int   g_srcid [E_MAX];                     // CSR: source node per slot
__device__ int   g_bsum  [SCAN_B];                    // scan block sums
__device__ float g_b2p[OUT];                          // bg@W2 + b2
__device__ int   g_is32;

// ---------------------------------------------------------------------------
// zero degree/cursor + dtype sniff (int32 read as int64 -> out-of-range)
// ---------------------------------------------------------------------------
__global__ void k_init(const long long* __restrict__ ei, int n, int E) {
    int i = blockIdx.x * blockDim.x + threadIdx.x;
    if (i < n) { g_degc[i] = 0; g_cursor[i] = 0; }
    if (blockIdx.x == 0 && threadIdx.x == 0) {
        int bad = 0;
        for (int j = 0; j < 16; j++) {
            long long a = ei[j], b = ei[E + j];
            if (a < 0 || a >= (long long)n) bad = 1;
            if (b < 0 || b >= (long long)n) bad = 1;
        }
        g_is32 = bad;
    }
}

__global__ void k_deg_count(const void* __restrict__ ei_raw, int E) {
    for (int e = blockIdx.x * blockDim.x + threadIdx.x; e < E;
         e += gridDim.x * blockDim.x) {
        int c;
        if (g_is32) c = ((const int*)ei_raw)[E + e];
        else        c = (int)((const long long*)ei_raw)[E + e];
        atomicAdd(&g_degc[c], 1);
    }
}

// ---- 3-kernel exclusive prefix scan of g_degc into g_start -----------------
__global__ void k_scan1(int n) {
    __shared__ int s[SCAN_B];
    int t = threadIdx.x, i = blockIdx.x * SCAN_B + t;
    int v = (i < n) ? g_degc[i] : 0;
    s[t] = v; __syncthreads();
    for (int off = 1; off < SCAN_B; off <<= 1) {
        int add = (t >= off) ? s[t - off] : 0;
        __syncthreads();
        s[t] += add;
        __syncthreads();
    }
    if (i < n) g_start[i] = s[t] - v;          // exclusive within chunk
    if (t == SCAN_B - 1) g_bsum[blockIdx.x] = s[t];
}

__global__ void k_scan2(int nb) {
    __shared__ int s[SCAN_B];
    int t = threadIdx.x;
    int v = (t < nb) ? g_bsum[t] : 0;
    s[t] = v; __syncthreads();
    for (int off = 1; off < SCAN_B; off <<= 1) {
        int add = (t >= off) ? s[t - off] : 0;
        __syncthreads();
        s[t] += add;
        __syncthreads();
    }
    if (t < nb) g_bsum[t] = s[t] - v;          // exclusive block offsets
}

__global__ void k_scan3(int n) {
    int i = blockIdx.x * blockDim.x + threadIdx.x;
    if (i < n) g_start[i] += g_bsum[i / SCAN_B];
}

// ---- fill CSR: g_srcid[start[c] + cursor[c]++] = r -------------------------
__global__ void k_fill(const void* __restrict__ ei_raw, int E) {
    for (int e = blockIdx.x * blockDim.x + threadIdx.x; e < E;
         e += gridDim.x * blockDim.x) {
        int r, c;
        if (g_is32) {
            const int* ei = (const int*)ei_raw;
            r = ei[e]; c = ei[E + e];
        } else {
            const long long* ei = (const long long*)ei_raw;
            r = (int)ei[e]; c = (int)ei[E + e];
        }
        int pos = g_start[c] + atomicAdd(&g_cursor[c], 1);
        g_srcid[pos] = r;
    }
}

// ---------------------------------------------------------------------------
// GEMM helpers: 4x4 register tile, float4 operand loads
// ---------------------------------------------------------------------------
__device__ __forceinline__ float f4c(float4 v, int k) {
    return (k == 0) ? v.x : (k == 1) ? v.y : (k == 2) ? v.z : v.w;
}

__device__ __forceinline__ void tile_fma(float acc[4][4], float4 w,
                                         float a0, float a1, float a2, float a3) {
    acc[0][0] = fmaf(a0, w.x, acc[0][0]); acc[0][1] = fmaf(a0, w.y, acc[0][1]);
    acc[0][2] = fmaf(a0, w.z, acc[0][2]); acc[0][3] = fmaf(a0, w.w, acc[0][3]);
    acc[1][0] = fmaf(a1, w.x, acc[1][0]); acc[1][1] = fmaf(a1, w.y, acc[1][1]);
    acc[1][2] = fmaf(a1, w.z, acc[1][2]); acc[1][3] = fmaf(a1, w.w, acc[1][3]);
    acc[2][0] = fmaf(a2, w.x, acc[2][0]); acc[2][1] = fmaf(a2, w.y, acc[2][1]);
    acc[2][2] = fmaf(a2, w.z, acc[2][2]); acc[2][3] = fmaf(a2, w.w, acc[2][3]);
    acc[3][0] = fmaf(a3, w.x, acc[3][0]); acc[3][1] = fmaf(a3, w.y, acc[3][1]);
    acc[3][2] = fmaf(a3, w.z, acc[3][2]); acc[3][3] = fmaf(a3, w.w, acc[3][3]);
}

__device__ __forceinline__ void gemm64(float acc[4][4], const float* sA,
                                       const float* sW, int r0, int c0, int wid) {
    #pragma unroll 4
    for (int k = 0; k < 64; k += 4) {
        float4 a0 = *(const float4*)(sA + (r0 + 0) * XS + k);
        float4 a1 = *(const float4*)(sA + (r0 + 1) * XS + k);
        float4 a2 = *(const float4*)(sA + (r0 + 2) * XS + k);
        float4 a3 = *(const float4*)(sA + (r0 + 3) * XS + k);
        #pragma unroll
        for (int kk = 0; kk < 4; kk++) {
            float4 w = *(const float4*)(sW + (k + kk) * wid + c0);
            tile_fma(acc, w, f4c(a0, kk), f4c(a1, kk), f4c(a2, kk), f4c(a3, kk));
        }
    }
}

// ---------------------------------------------------------------------------
// lin1: h1 = relu(x @ W1 + b1). 64x64 tile, 4x4 register tile, K in 2 chunks.
// ---------------------------------------------------------------------------
__global__ __launch_bounds__(256, 5) void k_lin1(const float* __restrict__ x,
                                                 const float* __restrict__ W1,
                                                 const float* __restrict__ b1,
                                                 int n) {
    __shared__ float sW[64 * HID];
    __shared__ float sX[64 * XS];
    const int tid = threadIdx.x;
    const int tx = tid & 15, ty = tid >> 4;
    const int n0 = blockIdx.x * 64;
    const int c0 = tx * 4, r0 = ty * 4;

    float4 bb = *(const float4*)(b1 + c0);
    float acc[4][4];
    #pragma unroll
    for (int i = 0; i < 4; i++) {
        acc[i][0] = bb.x; acc[i][1] = bb.y; acc[i][2] = bb.z; acc[i][3] = bb.w;
    }

    for (int kc = 0; kc < 2; kc++) {
        for (int i = tid; i < 64 * (HID / 4); i += 256)
            ((float4*)sW)[i] = ((const float4*)(W1 + kc * 64 * HID))[i];
        for (int i = tid; i < 64 * 16; i += 256) {
            int r = i >> 4, c4 = i & 15;
            int node = n0 + r;
            float4 v = (node < n)
                ? *(const float4*)(x + (size_t)node * IN_CH + kc * 64 + c4 * 4)
                : make_float4(0.f, 0.f, 0.f, 0.f);
            *(float4*)(sX + r * XS + c4 * 4) = v;
        }
        __syncthreads();
        gemm64(acc, sX, sW, r0, c0, HID);
        __syncthreads();
    }

    #pragma unroll
    for (int i = 0; i < 4; i++) {
        int node = n0 + r0 + i;
        if (node >= n) continue;
        float4 v = make_float4(fmaxf(acc[i][0], 0.f), fmaxf(acc[i][1], 0.f),
                               fmaxf(acc[i][2], 0.f), fmaxf(acc[i][3], 0.f));
        *(float4*)(g_h1 + (size_t)node * HID + c0) = v;
    }
}

// ---------------------------------------------------------------------------
// h2s = fp16( rsqrt(deg+1) * (h1 @ Wg) )   -- message payload stored as half
// ---------------------------------------------------------------------------
__global__ __launch_bounds__(256, 5) void k_h2s(const float* __restrict__ Wg, int n) {
    __shared__ float sW[HID * HID];
    __shared__ float sH[64 * XS];
    const int tid = threadIdx.x;
    const int tx = tid & 15, ty = tid >> 4;
    const int n0 = blockIdx.x * 64;
    const int c0 = tx * 4, r0 = ty * 4;

    for (int i = tid; i < HID * HID / 4; i += 256)
        ((float4*)sW)[i] = ((const float4*)Wg)[i];
    for (int i = tid; i < 64 * 16; i += 256) {
        int r = i >> 4, c4 = i & 15;
        int node = n0 + r;
        float4 v = (node < n)
            ? ((const float4*)(g_h1 + (size_t)node * HID))[c4]
            : make_float4(0.f, 0.f, 0.f, 0.f);
        *(float4*)(sH + r * XS + c4 * 4) = v;
    }
    __syncthreads();

    float acc[4][4];
    #pragma unroll
    for (int i = 0; i < 4; i++)
        #pragma unroll
        for (int j = 0; j < 4; j++) acc[i][j] = 0.f;

    gemm64(acc, sH, sW, r0, c0, HID);

    #pragma unroll
    for (int i = 0; i < 4; i++) {
        int node = n0 + r0 + i;
        if (node >= n) continue;
        float di = rsqrtf((float)(g_degc[node] + 1));
        __half2 h01 = __floats2half2_rn(acc[i][0] * di, acc[i][1] * di);
        __half2 h23 = __floats2half2_rn(acc[i][2] * di, acc[i][3] * di);
        __half2* dst = (__half2*)(g_h2s + (size_t)node * HID + c0);
        dst[0] = h01;
        dst[1] = h23;
    }
}

// ---------------------------------------------------------------------------
// CSR gather, 2 edges per warp-iteration:
//   lanes 0-15  handle edge j   (channel quad s = lane&15, 8B half4 each)
//   lanes 16-31 handle edge j+1
// After the loop, shfl_down(16) merges the two halves; lanes 0-15 add the
// self-loop and store float4 (fp32 accumulation throughout).
// ---------------------------------------------------------------------------
__global__ __launch_bounds__(256) void k_gather(int n) {
    const int warp = (blockIdx.x * 256 + threadIdx.x) >> 5;
    const int lane = threadIdx.x & 31;
    if (warp >= n) return;
    const int node = warp;
    const int beg = g_start[node];
    const int cnt = g_degc[node];
    const int g = lane >> 4;        // edge slot within pair
    const int s = lane & 15;        // channel quad

    const uint2* __restrict__ src = (const uint2*)g_h2s;  // 8B = 4 half
    float4 a = make_float4(0.f, 0.f, 0.f, 0.f);

    int j = 0;
    for (; j + 4 <= cnt; j += 4) {                        // 2 pairs unrolled
        int r0 = __ldg(&g_srcid[beg + j + g]);
        int r1 = __ldg(&g_srcid[beg + j + 2 + g]);
        uint2 p0 = __ldg(&src[(size_t)r0 * 16 + s]);
        uint2 p1 = __ldg(&src[(size_t)r1 * 16 + s]);
        float2 f0 = __half22float2(*(__half2*)&p0.x);
        float2 f1 = __half22float2(*(__half2*)&p0.y);
        float2 f2 = __half22float2(*(__half2*)&p1.x);
        float2 f3 = __half22float2(*(__half2*)&p1.y);
        a.x += f0.x + f2.x; a.y += f0.y + f2.y;
        a.z += f1.x + f3.x; a.w += f1.y + f3.y;
    }
    for (; j + 2 <= cnt; j += 2) {                        // one pair
        int r = __ldg(&g_srcid[beg + j + g]);
        uint2 p = __ldg(&src[(size_t)r * 16 + s]);
        float2 f0 = __half22float2(*(__half2*)&p.x);
        float2 f1 = __half22float2(*(__half2*)&p.y);
        a.x += f0.x; a.y += f0.y; a.z += f1.x; a.w += f1.y;
    }
    if (j < cnt && g == 0) {                              // odd tail
        int r = __ldg(&g_srcid[beg + j]);
        uint2 p = __ldg(&src[(size_t)r * 16 + s]);
        float2 f0 = __half22float2(*(__half2*)&p.x);
        float2 f1 = __half22float2(*(__half2*)&p.y);
        a.x += f0.x; a.y += f0.y; a.z += f1.x; a.w += f1.y;
    }

    // merge lane L and L+16
    a.x += __shfl_down_sync(0xffffffffu, a.x, 16);
    a.y += __shfl_down_sync(0xffffffffu, a.y, 16);
    a.z += __shfl_down_sync(0xffffffffu, a.z, 16);
    a.w += __shfl_down_sync(0xffffffffu, a.w, 16);

    if (g == 0) {
        uint2 p = __ldg(&src[(size_t)node * 16 + s]);     // self loop
        float2 f0 = __half22float2(*(__half2*)&p.x);
        float2 f1 = __half22float2(*(__half2*)&p.y);
        a.x += f0.x; a.y += f0.y; a.z += f1.x; a.w += f1.y;
        ((float4*)g_acc)[(size_t)node * 16 + s] = a;
    }
}

__global__ void k_b2p(const float* __restrict__ bg, const float* __restrict__ W2,
                      const float* __restrict__ b2) {
    int c = threadIdx.x;
    if (c < OUT) {
        float s = b2[c];
        #pragma unroll
        for (int k = 0; k < HID; k++) s = fmaf(bg[k], W2[k * OUT + c], s);
        g_b2p[c] = s;
    }
}

// ---------------------------------------------------------------------------
// out = (rsqrt(deg+1) * acc) @ W2 + b2'
// ---------------------------------------------------------------------------
__global__ __launch_bounds__(256, 5) void k_out(const float* __restrict__ W2,
                                                float* __restrict__ out, int n) {
    __shared__ float sW[HID * OUT];
    __shared__ float sA[64 * XS];
    const int tid = threadIdx.x;
    const int tx = tid & 15, ty = tid >> 4;
    const int n0 = blockIdx.x * 64;
    const int c0 = tx * 4, r0 = ty * 4;

    for (int i = tid; i < HID * OUT / 4; i += 256)
        ((float4*)sW)[i] = ((const float4*)W2)[i];
    for (int i = tid; i < 64 * 16; i += 256) {
        int r = i >> 4, c4 = i & 15;
        int node = n0 + r;
        float4 v = make_float4(0.f, 0.f, 0.f, 0.f);
        if (node < n) {
            v = ((const float4*)(g_acc + (size_t)node * HID))[c4];
            float di = rsqrtf((float)(g_degc[node] + 1));
            v.x *= di; v.y *= di; v.z *= di; v.w *= di;
        }
        *(float4*)(sA + r * XS + c4 * 4) = v;
    }
    __syncthreads();

    float4 bb = ((const float4*)g_b2p)[tx];
    float acc[4][4];
    #pragma unroll
    for (int i = 0; i < 4; i++) {
        acc[i][0] = bb.x; acc[i][1] = bb.y; acc[i][2] = bb.z; acc[i][3] = bb.w;
    }

    gemm64(acc, sA, sW, r0, c0, OUT);

    #pragma unroll
    for (int i = 0; i < 4; i++) {
        int node = n0 + r0 + i;
        if (node >= n) continue;
        float4 v = make_float4(acc[i][0], acc[i][1], acc[i][2], acc[i][3]);
        *(float4*)(out + (size_t)node * OUT + c0) = v;
    }
}

// ---------------------------------------------------------------------------
// Inputs (metadata order): x, edge_index, W1, b1, Wg, bg, W2, b2
// ---------------------------------------------------------------------------
extern "C" void kernel_launch(void* const* d_in, const int* in_sizes, int n_in,
                              void* d_out, int out_size) {
    const float* x  = (const float*)d_in[0];
    const void*  ei = d_in[1];
    const float* W1 = (const float*)d_in[2];
    const float* b1 = (const float*)d_in[3];
    const float* Wg = (const float*)d_in[4];
    const float* bg = (const float*)d_in[5];
    const float* W2 = (const float*)d_in[6];
    const float* b2 = (const float*)d_in[7];
    float* out = (float*)d_out;

    const int n = in_sizes[0] / IN_CH;   // 50000
    const int E = in_sizes[1] / 2;       // 1.6M
    const int nb = (n + SCAN_B - 1) / SCAN_B;

    k_init<<<(n + 255) / 256, 256>>>((const long long*)ei, n, E);   // 1
    k_b2p<<<1, 64>>>(bg, W2, b2);                                   // 2
    k_deg_count<<<2048, 256>>>(ei, E);                              // 3
    k_lin1<<<(n + 63) / 64, 256>>>(x, W1, b1, n);                   // 4 (profiled)
    k_scan1<<<nb, SCAN_B>>>(n);                                     // 5
    k_scan2<<<1, SCAN_B>>>(nb);                                     // 6
    k_scan3<<<nb, SCAN_B>>>(n);                                     // 7
    k_fill<<<2048, 256>>>(ei, E);                                   // 8
    k_h2s<<<(n + 63) / 64, 256>>>(Wg, n);                           // 9
    k_gather<<<(n * 32 + 255) / 256, 256>>>(n);                     // 10
    k_out<<<(n + 63) / 64, 256>>>(W2, out, n);                      // 11
}

// round 15
// speedup vs baseline: 2.3060x; 1.1028x over previous
#include <cuda_runtime.h>
#include <cuda_fp16.h>
#include <stdint.h>

#define N_MAX 50000
#define E_MAX 1600000
#define IN_CH 128
#define HID 64
#define OUT 64
#define XS 68        // smem row stride (floats) for 64-wide activation tiles
#define SCAN_B 256   // scan chunk

// ---- scratch (device globals: no allocation allowed) ----
__device__ __align__(16) __half g_h2s [N_MAX * HID];  // fp16(dinv * (relu(x@W1+b1)@Wg))
__device__ __align__(16) float  g_acc [N_MAX * HID];  // aggregated messages (fp32)
__device__ int   g_degc  [N_MAX];                     // edge in-degree (no self loop)
__device__ int   g_start [N_MAX];                     // CSR offsets (exclusive scan)
__device__ int   g_cursor[N_MAX];
__device__ int   g_srcid [E_MAX];                     // CSR: source node per slot
__device__ int   g_bsum  [SCAN_B];                    // scan block sums
__device__ float g_b2p[OUT];                          // bg@W2 + b2
__device__ int   g_is32;

// ---------------------------------------------------------------------------
// zero degree/cursor + dtype sniff (int32 read as int64 -> out-of-range)
// ---------------------------------------------------------------------------
__global__ void k_init(const long long* __restrict__ ei, int n, int E) {
    int i = blockIdx.x * blockDim.x + threadIdx.x;
    if (i < n) { g_degc[i] = 0; g_cursor[i] = 0; }
    if (blockIdx.x == 0 && threadIdx.x == 0) {
        int bad = 0;
        for (int j = 0; j < 16; j++) {
            long long a = ei[j], b = ei[E + j];
            if (a < 0 || a >= (long long)n) bad = 1;
            if (b < 0 || b >= (long long)n) bad = 1;
        }
        g_is32 = bad;
    }
}

__global__ void k_deg_count(const void* __restrict__ ei_raw, int E) {
    for (int e = blockIdx.x * blockDim.x + threadIdx.x; e < E;
         e += gridDim.x * blockDim.x) {
        int c;
        if (g_is32) c = ((const int*)ei_raw)[E + e];
        else        c = (int)((const long long*)ei_raw)[E + e];
        atomicAdd(&g_degc[c], 1);
    }
}

// ---- 3-kernel exclusive prefix scan of g_degc into g_start -----------------
__global__ void k_scan1(int n) {
    __shared__ int s[SCAN_B];
    int t = threadIdx.x, i = blockIdx.x * SCAN_B + t;
    int v = (i < n) ? g_degc[i] : 0;
    s[t] = v; __syncthreads();
    for (int off = 1; off < SCAN_B; off <<= 1) {
        int add = (t >= off) ? s[t - off] : 0;
        __syncthreads();
        s[t] += add;
        __syncthreads();
    }
    if (i < n) g_start[i] = s[t] - v;          // exclusive within chunk
    if (t == SCAN_B - 1) g_bsum[blockIdx.x] = s[t];
}

__global__ void k_scan2(int nb) {
    __shared__ int s[SCAN_B];
    int t = threadIdx.x;
    int v = (t < nb) ? g_bsum[t] : 0;
    s[t] = v; __syncthreads();
    for (int off = 1; off < SCAN_B; off <<= 1) {
        int add = (t >= off) ? s[t - off] : 0;
        __syncthreads();
        s[t] += add;
        __syncthreads();
    }
    if (t < nb) g_bsum[t] = s[t] - v;          // exclusive block offsets
}

__global__ void k_scan3(int n) {
    int i = blockIdx.x * blockDim.x + threadIdx.x;
    if (i < n) g_start[i] += g_bsum[i / SCAN_B];
}

// ---- fill CSR: g_srcid[start[c] + cursor[c]++] = r -------------------------
__global__ void k_fill(const void* __restrict__ ei_raw, int E) {
    for (int e = blockIdx.x * blockDim.x + threadIdx.x; e < E;
         e += gridDim.x * blockDim.x) {
        int r, c;
        if (g_is32) {
            const int* ei = (const int*)ei_raw;
            r = ei[e]; c = ei[E + e];
        } else {
            const long long* ei = (const long long*)ei_raw;
            r = (int)ei[e]; c = (int)ei[E + e];
        }
        int pos = g_start[c] + atomicAdd(&g_cursor[c], 1);
        g_srcid[pos] = r;
    }
}

// ---------------------------------------------------------------------------
// GEMM helpers: 4x4 register tile, float4 operand loads
// ---------------------------------------------------------------------------
__device__ __forceinline__ float f4c(float4 v, int k) {
    return (k == 0) ? v.x : (k == 1) ? v.y : (k == 2) ? v.z : v.w;
}

__device__ __forceinline__ void tile_fma(float acc[4][4], float4 w,
                                         float a0, float a1, float a2, float a3) {
    acc[0][0] = fmaf(a0, w.x, acc[0][0]); acc[0][1] = fmaf(a0, w.y, acc[0][1]);
    acc[0][2] = fmaf(a0, w.z, acc[0][2]); acc[0][3] = fmaf(a0, w.w, acc[0][3]);
    acc[1][0] = fmaf(a1, w.x, acc[1][0]); acc[1][1] = fmaf(a1, w.y, acc[1][1]);
    acc[1][2] = fmaf(a1, w.z, acc[1][2]); acc[1][3] = fmaf(a1, w.w, acc[1][3]);
    acc[2][0] = fmaf(a2, w.x, acc[2][0]); acc[2][1] = fmaf(a2, w.y, acc[2][1]);
    acc[2][2] = fmaf(a2, w.z, acc[2][2]); acc[2][3] = fmaf(a2, w.w, acc[2][3]);
    acc[3][0] = fmaf(a3, w.x, acc[3][0]); acc[3][1] = fmaf(a3, w.y, acc[3][1]);
    acc[3][2] = fmaf(a3, w.z, acc[3][2]); acc[3][3] = fmaf(a3, w.w, acc[3][3]);
}

__device__ __forceinline__ void gemm64(float acc[4][4], const float* sA,
                                       const float* sW, int r0, int c0, int wid) {
    #pragma unroll 4
    for (int k = 0; k < 64; k += 4) {
        float4 a0 = *(const float4*)(sA + (r0 + 0) * XS + k);
        float4 a1 = *(const float4*)(sA + (r0 + 1) * XS + k);
        float4 a2 = *(const float4*)(sA + (r0 + 2) * XS + k);
        float4 a3 = *(const float4*)(sA + (r0 + 3) * XS + k);
        #pragma unroll
        for (int kk = 0; kk < 4; kk++) {
            float4 w = *(const float4*)(sW + (k + kk) * wid + c0);
            tile_fma(acc, w, f4c(a0, kk), f4c(a1, kk), f4c(a2, kk), f4c(a3, kk));
        }
    }
}

// ---------------------------------------------------------------------------
// FUSED lin1+h2s: h2s = fp16( rsqrt(deg+1) * (relu(x@W1+b1) @ Wg) )
// 64x64 tile, 4x4 register tile. Phase 1 consumes x in two K-chunks;
// relu result is written back into sX (in place), Wg replaces sW,
// phase 2 runs from smem. h1 never touches global memory.
// Static smem: sW 16KB + sX 17.4KB = 33.4KB.
// ---------------------------------------------------------------------------
__global__ __launch_bounds__(256) void k_l1h2(const float* __restrict__ x,
                                              const float* __restrict__ W1,
                                              const float* __restrict__ b1,
                                              const float* __restrict__ Wg,
                                              int n) {
    __shared__ float sW[64 * HID];
    __shared__ float sX[64 * XS];
    const int tid = threadIdx.x;
    const int tx = tid & 15, ty = tid >> 4;
    const int n0 = blockIdx.x * 64;
    const int c0 = tx * 4, r0 = ty * 4;

    // ---- phase 1: acc = x @ W1 + b1
    float4 bb = *(const float4*)(b1 + c0);
    float acc[4][4];
    #pragma unroll
    for (int i = 0; i < 4; i++) {
        acc[i][0] = bb.x; acc[i][1] = bb.y; acc[i][2] = bb.z; acc[i][3] = bb.w;
    }

    for (int kc = 0; kc < 2; kc++) {
        for (int i = tid; i < 64 * (HID / 4); i += 256)
            ((float4*)sW)[i] = ((const float4*)(W1 + kc * 64 * HID))[i];
        for (int i = tid; i < 64 * 16; i += 256) {
            int r = i >> 4, c4 = i & 15;
            int node = n0 + r;
            float4 v = (node < n)
                ? *(const float4*)(x + (size_t)node * IN_CH + kc * 64 + c4 * 4)
                : make_float4(0.f, 0.f, 0.f, 0.f);
            *(float4*)(sX + r * XS + c4 * 4) = v;
        }
        __syncthreads();
        gemm64(acc, sX, sW, r0, c0, HID);
        __syncthreads();
    }

    // ---- handoff: sX <- relu(acc), sW <- Wg
    #pragma unroll
    for (int i = 0; i < 4; i++) {
        float4 v = make_float4(fmaxf(acc[i][0], 0.f), fmaxf(acc[i][1], 0.f),
                               fmaxf(acc[i][2], 0.f), fmaxf(acc[i][3], 0.f));
        *(float4*)(sX + (r0 + i) * XS + c0) = v;
    }
    for (int i = tid; i < HID * HID / 4; i += 256)
        ((float4*)sW)[i] = ((const float4*)Wg)[i];
    __syncthreads();

    // ---- phase 2: h2 = h1 @ Wg, scale by dinv, store fp16
    #pragma unroll
    for (int i = 0; i < 4; i++)
        #pragma unroll
        for (int j = 0; j < 4; j++) acc[i][j] = 0.f;

    gemm64(acc, sX, sW, r0, c0, HID);

    #pragma unroll
    for (int i = 0; i < 4; i++) {
        int node = n0 + r0 + i;
        if (node >= n) continue;
        float di = rsqrtf((float)(g_degc[node] + 1));
        __half2 h01 = __floats2half2_rn(acc[i][0] * di, acc[i][1] * di);
        __half2 h23 = __floats2half2_rn(acc[i][2] * di, acc[i][3] * di);
        __half2* dst = (__half2*)(g_h2s + (size_t)node * HID + c0);
        dst[0] = h01;
        dst[1] = h23;
    }
}

// ---------------------------------------------------------------------------
// CSR gather, 2 edges per warp-iteration:
//   lanes 0-15  handle edge j   (channel quad s = lane&15, 8B half4 each)
//   lanes 16-31 handle edge j+1
// shfl_down(16) merges halves; lanes 0-15 add self-loop, store float4.
// ---------------------------------------------------------------------------
__global__ __launch_bounds__(256) void k_gather(int n) {
    const int warp = (blockIdx.x * 256 + threadIdx.x) >> 5;
    const int lane = threadIdx.x & 31;
    if (warp >= n) return;
    const int node = warp;
    const int beg = g_start[node];
    const int cnt = g_degc[node];
    const int g = lane >> 4;        // edge slot within pair
    const int s = lane & 15;        // channel quad

    const uint2* __restrict__ src = (const uint2*)g_h2s;  // 8B = 4 half
    float4 a = make_float4(0.f, 0.f, 0.f, 0.f);

    int j = 0;
    for (; j + 4 <= cnt; j += 4) {                        // 2 pairs unrolled
        int r0 = __ldg(&g_srcid[beg + j + g]);
        int r1 = __ldg(&g_srcid[beg + j + 2 + g]);
        uint2 p0 = __ldg(&src[(size_t)r0 * 16 + s]);
        uint2 p1 = __ldg(&src[(size_t)r1 * 16 + s]);
        float2 f0 = __half22float2(*(__half2*)&p0.x);
        float2 f1 = __half22float2(*(__half2*)&p0.y);
        float2 f2 = __half22float2(*(__half2*)&p1.x);
        float2 f3 = __half22float2(*(__half2*)&p1.y);
        a.x += f0.x + f2.x; a.y += f0.y + f2.y;
        a.z += f1.x + f3.x; a.w += f1.y + f3.y;
    }
    for (; j + 2 <= cnt; j += 2) {                        // one pair
        int r = __ldg(&g_srcid[beg + j + g]);
        uint2 p = __ldg(&src[(size_t)r * 16 + s]);
        float2 f0 = __half22float2(*(__half2*)&p.x);
        float2 f1 = __half22float2(*(__half2*)&p.y);
        a.x += f0.x; a.y += f0.y; a.z += f1.x; a.w += f1.y;
    }
    if (j < cnt && g == 0) {                              // odd tail
        int r = __ldg(&g_srcid[beg + j]);
        uint2 p = __ldg(&src[(size_t)r * 16 + s]);
        float2 f0 = __half22float2(*(__half2*)&p.x);
        float2 f1 = __half22float2(*(__half2*)&p.y);
        a.x += f0.x; a.y += f0.y; a.z += f1.x; a.w += f1.y;
    }

    a.x += __shfl_down_sync(0xffffffffu, a.x, 16);
    a.y += __shfl_down_sync(0xffffffffu, a.y, 16);
    a.z += __shfl_down_sync(0xffffffffu, a.z, 16);
    a.w += __shfl_down_sync(0xffffffffu, a.w, 16);

    if (g == 0) {
        uint2 p = __ldg(&src[(size_t)node * 16 + s]);     // self loop
        float2 f0 = __half22float2(*(__half2*)&p.x);
        float2 f1 = __half22float2(*(__half2*)&p.y);
        a.x += f0.x; a.y += f0.y; a.z += f1.x; a.w += f1.y;
        ((float4*)g_acc)[(size_t)node * 16 + s] = a;
    }
}

__global__ void k_b2p(const float* __restrict__ bg, const float* __restrict__ W2,
                      const float* __restrict__ b2) {
    int c = threadIdx.x;
    if (c < OUT) {
        float s = b2[c];
        #pragma unroll
        for (int k = 0; k < HID; k++) s = fmaf(bg[k], W2[k * OUT + c], s);
        g_b2p[c] = s;
    }
}

// ---------------------------------------------------------------------------
// out = (rsqrt(deg+1) * acc) @ W2 + b2'
// ---------------------------------------------------------------------------
__global__ __launch_bounds__(256) void k_out(const float* __restrict__ W2,
                                             float* __restrict__ out, int n) {
    __shared__ float sW[HID * OUT];
    __shared__ float sA[64 * XS];
    const int tid = threadIdx.x;
    const int tx = tid & 15, ty = tid >> 4;
    const int n0 = blockIdx.x * 64;
    const int c0 = tx * 4, r0 = ty * 4;

    for (int i = tid; i < HID * OUT / 4; i += 256)
        ((float4*)sW)[i] = ((const float4*)W2)[i];
    for (int i = tid; i < 64 * 16; i += 256) {
        int r = i >> 4, c4 = i & 15;
        int node = n0 + r;
        float4 v = make_float4(0.f, 0.f, 0.f, 0.f);
        if (node < n) {
            v = ((const float4*)(g_acc + (size_t)node * HID))[c4];
            float di = rsqrtf((float)(g_degc[node] + 1));
            v.x *= di; v.y *= di; v.z *= di; v.w *= di;
        }
        *(float4*)(sA + r * XS + c4 * 4) = v;
    }
    __syncthreads();

    float4 bb = ((const float4*)g_b2p)[tx];
    float acc[4][4];
    #pragma unroll
    for (int i = 0; i < 4; i++) {
        acc[i][0] = bb.x; acc[i][1] = bb.y; acc[i][2] = bb.z; acc[i][3] = bb.w;
    }

    gemm64(acc, sA, sW, r0, c0, OUT);

    #pragma unroll
    for (int i = 0; i < 4; i++) {
        int node = n0 + r0 + i;
        if (node >= n) continue;
        float4 v = make_float4(acc[i][0], acc[i][1], acc[i][2], acc[i][3]);
        *(float4*)(out + (size_t)node * OUT + c0) = v;
    }
}

// ---------------------------------------------------------------------------
// Inputs (metadata order): x, edge_index, W1, b1, Wg, bg, W2, b2
// ---------------------------------------------------------------------------
extern "C" void kernel_launch(void* const* d_in, const int* in_sizes, int n_in,
                              void* d_out, int out_size) {
    const float* x  = (const float*)d_in[0];
    const void*  ei = d_in[1];
    const float* W1 = (const float*)d_in[2];
    const float* b1 = (const float*)d_in[3];
    const float* Wg = (const float*)d_in[4];
    const float* bg = (const float*)d_in[5];
    const float* W2 = (const float*)d_in[6];
    const float* b2 = (const float*)d_in[7];
    float* out = (float*)d_out;

    const int n = in_sizes[0] / IN_CH;   // 50000
    const int E = in_sizes[1] / 2;       // 1.6M
    const int nb = (n + SCAN_B - 1) / SCAN_B;

    k_init<<<(n + 255) / 256, 256>>>((const long long*)ei, n, E);   // 1
    k_b2p<<<1, 64>>>(bg, W2, b2);                                   // 2
    k_deg_count<<<2048, 256>>>(ei, E);                              // 3
    k_l1h2<<<(n + 63) / 64, 256>>>(x, W1, b1, Wg, n);               // 4 (profiled)
    k_scan1<<<nb, SCAN_B>>>(n);                                     // 5
    k_scan2<<<1, SCAN_B>>>(nb);                                     // 6
    k_scan3<<<nb, SCAN_B>>>(n);                                     // 7
    k_fill<<<2048, 256>>>(ei, E);                                   // 8
    k_gather<<<(n * 32 + 255) / 256, 256>>>(n);                     // 9
    k_out<<<(n + 63) / 64, 256>>>(W2, out, n);                      // 10
}